// round 13
// baseline (speedup 1.0000x reference)
#include <cuda_runtime.h>
#include <cuda_fp16.h>
#include <math.h>
#include <stdint.h>

#define NB   8
#define SS   4096
#define DD   1024
#define DKK  512
#define NH   8
#define WW   128
#define DH   64
#define NWIN 32   // S / W

// fp16 operand buffers (device globals: allowed)
__device__ __half g_Bqk[(size_t)NB * DD * SS];
__device__ __half g_Bv [(size_t)NB * DD * SS];
__device__ __half g_Bo [(size_t)NB * DKK * SS];
__device__ __half g_Qh[(size_t)NB * DKK * SS], g_Ql[(size_t)NB * DKK * SS];
__device__ __half g_Kh[(size_t)NB * DKK * SS], g_Kl[(size_t)NB * DKK * SS];
__device__ __half g_Vh[(size_t)NB * DKK * SS], g_Vl[(size_t)NB * DKK * SS];
__device__ __half g_Wqh[DKK * DD];
__device__ __half g_Wkh[DKK * DD];
__device__ __half g_Wvh[DKK * DD];
__device__ __half g_Woh[DD * DKK];

// ============================================================================
// PTX helpers (sm_80+ only — compute_103-safe)
// ============================================================================
__device__ __forceinline__ uint32_t smem_u32(const void* p) {
    uint32_t a;
    asm("{ .reg .u64 t; cvta.to.shared.u64 t, %1; cvt.u32.u64 %0, t; }"
        : "=r"(a) : "l"(p));
    return a;
}
__device__ __forceinline__ void ldsm_x4(uint32_t* r, uint32_t addr) {
    asm volatile("ldmatrix.sync.aligned.m8n8.x4.shared.b16 {%0,%1,%2,%3}, [%4];"
                 : "=r"(r[0]), "=r"(r[1]), "=r"(r[2]), "=r"(r[3]) : "r"(addr));
}
__device__ __forceinline__ void ldsm_x4_t(uint32_t* r, uint32_t addr) {
    asm volatile("ldmatrix.sync.aligned.m8n8.x4.trans.shared.b16 {%0,%1,%2,%3}, [%4];"
                 : "=r"(r[0]), "=r"(r[1]), "=r"(r[2]), "=r"(r[3]) : "r"(addr));
}
__device__ __forceinline__ void mma16816(float* d, const uint32_t* a, const uint32_t* b) {
    asm volatile(
        "mma.sync.aligned.m16n8k16.row.col.f32.f16.f16.f32 "
        "{%0,%1,%2,%3},{%4,%5,%6,%7},{%8,%9},{%0,%1,%2,%3};"
        : "+f"(d[0]), "+f"(d[1]), "+f"(d[2]), "+f"(d[3])
        : "r"(a[0]), "r"(a[1]), "r"(a[2]), "r"(a[3]), "r"(b[0]), "r"(b[1]));
}
__device__ __forceinline__ void cp_async16(uint32_t dst, const void* src) {
    asm volatile("cp.async.cg.shared.global [%0], [%1], 16;" :: "r"(dst), "l"(src));
}
__device__ __forceinline__ void cp_commit() {
    asm volatile("cp.async.commit_group;" ::: "memory");
}
template<int N> __device__ __forceinline__ void cp_wait() {
    asm volatile("cp.async.wait_group %0;" :: "n"(N) : "memory");
}
__device__ __forceinline__ float gelu_exact(float x) { return x * normcdff(x); }

// ============================================================================
// Conversion kernels (merged)
// ============================================================================
__global__ void cvt_w4(const float4* __restrict__ s0, const float4* __restrict__ s1,
                       const float4* __restrict__ s2, const float4* __restrict__ s3,
                       uint2* __restrict__ d0, uint2* __restrict__ d1,
                       uint2* __restrict__ d2, uint2* __restrict__ d3)
{
    int i = blockIdx.x * blockDim.x + threadIdx.x;   // 4 * 131072 total
    int w = i >> 17, j = i & 131071;
    const float4* s = (w == 0) ? s0 : (w == 1) ? s1 : (w == 2) ? s2 : s3;
    uint2* d = (w == 0) ? d0 : (w == 1) ? d1 : (w == 2) ? d2 : d3;
    float4 v = s[j];
    unsigned h0 = __half_as_ushort(__float2half_rn(v.x));
    unsigned h1 = __half_as_ushort(__float2half_rn(v.y));
    unsigned h2 = __half_as_ushort(__float2half_rn(v.z));
    unsigned h3 = __half_as_ushort(__float2half_rn(v.w));
    d[j] = make_uint2(h0 | (h1 << 16), h2 | (h3 << 16));
}

__global__ void cvt_x2(const float4* __restrict__ s0, const float4* __restrict__ s1,
                       uint2* __restrict__ d0, uint2* __restrict__ d1, int n4)
{
    int i = blockIdx.x * blockDim.x + threadIdx.x;   // 2 * n4 total
    int w = (i >= n4), j = w ? (i - n4) : i;
    const float4* s = w ? s1 : s0;
    uint2* d = w ? d1 : d0;
    float4 v = s[j];
    unsigned h0 = __half_as_ushort(__float2half_rn(v.x));
    unsigned h1 = __half_as_ushort(__float2half_rn(v.y));
    unsigned h2 = __half_as_ushort(__float2half_rn(v.z));
    unsigned h3 = __half_as_ushort(__float2half_rn(v.w));
    d[j] = make_uint2(h0 | (h1 << 16), h2 | (h3 << 16));
}

// ============================================================================
// GEMM smem layout: CTA tile 256x128, K-chunk 32.
// A smem [m(256)][k(32)] pitch 80B; B smem [k(32)][n(128)] pitch 272B.
// ============================================================================
#define OFF_AH   0
#define OFF_BH   20480                      // 256*80
#define STAGE_SZ 29184                      // + 32*272
#define NSTAGE   3
#define GSMEM_TOTAL (NSTAGE * STAGE_SZ)

// ============================================================================
// Merged QKV GEMM: grid (32, 6, NB). seg = by>>1 selects Q/K/V; m0=(by&1)*256.
// Warp grid 4m x 2n, warp tile 64x64. C written fp16 hi/lo.
// ============================================================================
__global__ __launch_bounds__(256, 1) void gemm_qkv(
    const float* __restrict__ bq, const float* __restrict__ bk,
    const float* __restrict__ bv)
{
    extern __shared__ char sm[];
    const int tid  = threadIdx.x;
    const int warp = tid >> 5;
    const int lane = tid & 31;
    const int bx = blockIdx.x, by = blockIdx.y, bz = blockIdx.z;
    const int seg = by >> 1;
    const int n0 = bx * 128, m0 = (by & 1) * 256;
    const int wm = (warp >> 1) * 64;     // 4 m-warps of 64
    const int wn = (warp & 1) * 64;      // 2 n-warps of 64
    const int M = DKK, N = SS, K = DD;

    const __half* Ah  = (seg == 0) ? g_Wqh : (seg == 1) ? g_Wkh : g_Wvh;
    const __half* Bgl = (seg == 2) ? g_Bv : g_Bqk;
    const float* bias = (seg == 0) ? bq : (seg == 1) ? bk : bv;
    __half* Ch = ((seg == 0) ? g_Qh : (seg == 1) ? g_Kh : g_Vh) + (size_t)bz * M * N;
    __half* Cl = ((seg == 0) ? g_Ql : (seg == 1) ? g_Kl : g_Vl) + (size_t)bz * M * N;

    const __half* Bb = Bgl + (size_t)bz * K * N;
    const uint32_t smb = smem_u32(sm);

    const int ar = tid >> 2, aq = tid & 3;     // A: 64 rows/iter x 4 16B groups
    const int br = tid >> 4, bq2 = tid & 15;   // B: 16 rows/iter x 16 16B groups

    auto issue = [&](int c, int st) {
        const uint32_t sb = smb + st * STAGE_SZ;
        const __half* Ahp = Ah + (size_t)m0 * K + c * 32;
        const __half* Bp  = Bb + (size_t)(c * 32) * N + n0;
        #pragma unroll
        for (int it = 0; it < 4; it++) {
            int r = ar + it * 64;              // 0..255
            cp_async16(sb + OFF_AH + (uint32_t)(r * 80 + aq * 16),
                       Ahp + (size_t)r * K + aq * 8);
        }
        #pragma unroll
        for (int it = 0; it < 2; it++) {
            int rb = br + it * 16;             // 0..31
            cp_async16(sb + OFF_BH + (uint32_t)(rb * 272 + bq2 * 16),
                       Bp + (size_t)rb * N + bq2 * 8);
        }
    };

    float acc[4][8][4];
    #pragma unroll
    for (int i = 0; i < 4; i++)
        #pragma unroll
        for (int j = 0; j < 8; j++)
            #pragma unroll
            for (int t = 0; t < 4; t++) acc[i][j][t] = 0.f;

    const int nch = K >> 5;
    issue(0, 0); cp_commit();
    issue(1, 1); cp_commit();

    const int lrow16 = lane & 15;
    const int khalf  = (lane >> 4) * 8;
    const uint32_t l7 = lane & 7, mh = (lane >> 3) & 1, kh = (lane >> 4) & 1;

    for (int c = 0; c < nch; c++) {
        cp_wait<1>();
        __syncthreads();
        if (c + 2 < nch) issue(c + 2, (c + 2) % NSTAGE);
        cp_commit();

        const uint32_t bb = smb + (c % NSTAGE) * STAGE_SZ;
        #pragma unroll
        for (int s = 0; s < 2; s++) {
            const int ks = s * 16;
            uint32_t bh[4][4];
            const uint32_t brow = (uint32_t)((ks + mh * 8 + l7) * 272);
            #pragma unroll
            for (int nj = 0; nj < 4; nj++)
                ldsm_x4_t(bh[nj], bb + OFF_BH + brow +
                          (uint32_t)((wn + nj * 16 + kh * 8) * 2));
            #pragma unroll
            for (int mi = 0; mi < 4; mi++) {
                uint32_t ah[4];
                const uint32_t aoff =
                    (uint32_t)((wm + mi * 16 + lrow16) * 80 + (ks + khalf) * 2);
                ldsm_x4(ah, bb + OFF_AH + aoff);
                #pragma unroll
                for (int nj = 0; nj < 4; nj++) {
                    mma16816(acc[mi][nj * 2],     ah, bh[nj]);
                    mma16816(acc[mi][nj * 2 + 1], ah, bh[nj] + 2);
                }
            }
        }
    }

    const int r_in = lane >> 2;
    const int c_in = (lane & 3) * 2;
    #pragma unroll
    for (int mi = 0; mi < 4; mi++) {
        const int r0 = m0 + wm + mi * 16 + r_in;
        const float b0 = bias[r0];
        const float b1 = bias[r0 + 8];
        #pragma unroll
        for (int ni = 0; ni < 8; ni++) {
            const int col = n0 + wn + ni * 8 + c_in;
            float v0 = acc[mi][ni][0] + b0, v1 = acc[mi][ni][1] + b0;
            float v2 = acc[mi][ni][2] + b1, v3 = acc[mi][ni][3] + b1;
            __half h0 = __float2half_rn(v0), h1 = __float2half_rn(v1);
            __half h2 = __float2half_rn(v2), h3 = __float2half_rn(v3);
            __half l0 = __float2half_rn(__fsub_rn(v0, __half2float(h0)));
            __half l1 = __float2half_rn(__fsub_rn(v1, __half2float(h1)));
            __half l2 = __float2half_rn(__fsub_rn(v2, __half2float(h2)));
            __half l3 = __float2half_rn(__fsub_rn(v3, __half2float(h3)));
            *(__half2*)(Ch + (size_t)r0 * N + col)       = __halves2half2(h0, h1);
            *(__half2*)(Cl + (size_t)r0 * N + col)       = __halves2half2(l0, l1);
            *(__half2*)(Ch + (size_t)(r0 + 8) * N + col) = __halves2half2(h2, h3);
            *(__half2*)(Cl + (size_t)(r0 + 8) * N + col) = __halves2half2(l2, l3);
        }
    }
}

// ============================================================================
// Final projection GEMM: grid (32, 4, NB), CTA 256x128, fp32 out with mask.
// ============================================================================
__global__ __launch_bounds__(256, 1) void gemm_out(
    const float* __restrict__ bias, const float* __restrict__ cmask,
    float* __restrict__ C)
{
    extern __shared__ char sm[];
    const int tid  = threadIdx.x;
    const int warp = tid >> 5;
    const int lane = tid & 31;
    const int bx = blockIdx.x, by = blockIdx.y, bz = blockIdx.z;
    const int n0 = bx * 128, m0 = by * 256;
    const int wm = (warp >> 1) * 64;
    const int wn = (warp & 1) * 64;
    const int M = DD, N = SS, K = DKK;

    const __half* Bb = g_Bo + (size_t)bz * K * N;
    const uint32_t smb = smem_u32(sm);

    const int ar = tid >> 2, aq = tid & 3;
    const int br = tid >> 4, bq2 = tid & 15;

    auto issue = [&](int c, int st) {
        const uint32_t sb = smb + st * STAGE_SZ;
        const __half* Ahp = g_Woh + (size_t)m0 * K + c * 32;
        const __half* Bp  = Bb + (size_t)(c * 32) * N + n0;
        #pragma unroll
        for (int it = 0; it < 4; it++) {
            int r = ar + it * 64;
            cp_async16(sb + OFF_AH + (uint32_t)(r * 80 + aq * 16),
                       Ahp + (size_t)r * K + aq * 8);
        }
        #pragma unroll
        for (int it = 0; it < 2; it++) {
            int rb = br + it * 16;
            cp_async16(sb + OFF_BH + (uint32_t)(rb * 272 + bq2 * 16),
                       Bp + (size_t)rb * N + bq2 * 8);
        }
    };

    float acc[4][8][4];
    #pragma unroll
    for (int i = 0; i < 4; i++)
        #pragma unroll
        for (int j = 0; j < 8; j++)
            #pragma unroll
            for (int t = 0; t < 4; t++) acc[i][j][t] = 0.f;

    const int nch = K >> 5;
    issue(0, 0); cp_commit();
    issue(1, 1); cp_commit();

    const int lrow16 = lane & 15;
    const int khalf  = (lane >> 4) * 8;
    const uint32_t l7 = lane & 7, mh = (lane >> 3) & 1, kh = (lane >> 4) & 1;

    for (int c = 0; c < nch; c++) {
        cp_wait<1>();
        __syncthreads();
        if (c + 2 < nch) issue(c + 2, (c + 2) % NSTAGE);
        cp_commit();

        const uint32_t bb = smb + (c % NSTAGE) * STAGE_SZ;
        #pragma unroll
        for (int s = 0; s < 2; s++) {
            const int ks = s * 16;
            uint32_t bh[4][4];
            const uint32_t brow = (uint32_t)((ks + mh * 8 + l7) * 272);
            #pragma unroll
            for (int nj = 0; nj < 4; nj++)
                ldsm_x4_t(bh[nj], bb + OFF_BH + brow +
                          (uint32_t)((wn + nj * 16 + kh * 8) * 2));
            #pragma unroll
            for (int mi = 0; mi < 4; mi++) {
                uint32_t ah[4];
                const uint32_t aoff =
                    (uint32_t)((wm + mi * 16 + lrow16) * 80 + (ks + khalf) * 2);
                ldsm_x4(ah, bb + OFF_AH + aoff);
                #pragma unroll
                for (int nj = 0; nj < 4; nj++) {
                    mma16816(acc[mi][nj * 2],     ah, bh[nj]);
                    mma16816(acc[mi][nj * 2 + 1], ah, bh[nj] + 2);
                }
            }
        }
    }

    const int r_in = lane >> 2;
    const int c_in = (lane & 3) * 2;
    float* Cb = C + (size_t)bz * M * N;
    #pragma unroll
    for (int mi = 0; mi < 4; mi++) {
        const int r0 = m0 + wm + mi * 16 + r_in;
        const float b0 = bias[r0];
        const float b1 = bias[r0 + 8];
        #pragma unroll
        for (int ni = 0; ni < 8; ni++) {
            const int col = n0 + wn + ni * 8 + c_in;
            float m0f = cmask[(size_t)bz * N + col];
            float m1f = cmask[(size_t)bz * N + col + 1];
            *(float2*)(Cb + (size_t)r0 * N + col) =
                make_float2((acc[mi][ni][0] + b0) * m0f, (acc[mi][ni][1] + b0) * m1f);
            *(float2*)(Cb + (size_t)(r0 + 8) * N + col) =
                make_float2((acc[mi][ni][2] + b1) * m0f, (acc[mi][ni][3] + b1) * m1f);
        }
    }
}

// ============================================================================
// Tensor-core windowed attention, register-resident P (unchanged from R11):
// QK^T (3-pass) -> warp-local softmax -> P hi/lo in registers ->
// O^T = P @ V^T (3-pass) -> /sum, GELU, fp16 store.
// ============================================================================
#define AT_QH  0
#define AT_QL  17408
#define AT_KH  34816
#define AT_KL  52224
#define AT_VH  69632
#define AT_VL  87040
#define AT_MSK 104448   // float[128]
#define AT_SMEM 104960

__global__ __launch_bounds__(256, 2) void attn_mma(const float* __restrict__ masks)
{
    extern __shared__ char sm[];
    const uint32_t smb = smem_u32(sm);
    const int tid = threadIdx.x, warp = tid >> 5, lane = tid & 31;
    const int wh = blockIdx.x, w = wh >> 3, h = wh & 7, b = blockIdx.y;
    const size_t base = ((size_t)b * DKK + h * 64) * SS + (size_t)w * WW;

    {
        const __half* srcs[6] = { g_Qh + base, g_Ql + base, g_Kh + base,
                                  g_Kl + base, g_Vh + base, g_Vl + base };
        #pragma unroll
        for (int t = 0; t < 6; t++) {
            const uint32_t dstb = smb + t * 17408;
            #pragma unroll
            for (int it = 0; it < 4; it++) {
                int idx = tid + it * 256;
                int row = idx >> 4, ch = idx & 15;
                cp_async16(dstb + row * 272 + ch * 16,
                           srcs[t] + (size_t)row * SS + ch * 8);
            }
        }
        cp_commit();
    }
    if (tid < 32) {
        float4 mv = *(const float4*)(masks + (size_t)b * SS + w * WW + tid * 4);
        *(float4*)(sm + AT_MSK + tid * 16) = mv;
    }
    cp_wait<0>();
    __syncthreads();

    const int r_in = lane >> 2, c_in = (lane & 3) * 2;
    const uint32_t l7 = lane & 7, mh = (lane >> 3) & 1, kh = (lane >> 4) & 1;
    const int i0w = warp * 16;

    // ---- QK^T ----
    float acc[16][4];
    #pragma unroll
    for (int f = 0; f < 16; f++)
        #pragma unroll
        for (int t = 0; t < 4; t++) acc[f][t] = 0.f;

    #pragma unroll
    for (int s = 0; s < 4; s++) {
        uint32_t ah[4], al[4];
        const uint32_t aaddr = smb + (s * 16 + kh * 8 + l7) * 272 + (i0w + mh * 8) * 2;
        ldsm_x4_t(ah, aaddr + AT_QH);
        ldsm_x4_t(al, aaddr + AT_QL);
        #pragma unroll
        for (int q = 0; q < 8; q++) {
            const uint32_t baddr = smb + AT_KH +
                (s * 16 + mh * 8 + l7) * 272 + (q * 16 + kh * 8) * 2;
            uint32_t bh4[4], bl4[4];
            ldsm_x4_t(bh4, baddr);
            ldsm_x4_t(bl4, baddr + (AT_KL - AT_KH));
            const int f0 = q * 2;
            mma16816(acc[f0],     ah, bh4);
            mma16816(acc[f0],     al, bh4);
            mma16816(acc[f0],     ah, bl4);
            mma16816(acc[f0 + 1], ah, bh4 + 2);
            mma16816(acc[f0 + 1], al, bh4 + 2);
            mma16816(acc[f0 + 1], ah, bl4 + 2);
        }
    }

    // ---- mask + scale + warp-local softmax ----
    const float* mk = (const float*)(sm + AT_MSK);
    float mx0 = -1e30f, mx1 = -1e30f;
    #pragma unroll
    for (int f = 0; f < 16; f++) {
        const int j = f * 8 + c_in;
        const float mj0 = mk[j], mj1 = mk[j + 1];
        acc[f][0] = (mj0 > 0.f) ? acc[f][0] * 0.125f : -1e9f;
        acc[f][1] = (mj1 > 0.f) ? acc[f][1] * 0.125f : -1e9f;
        acc[f][2] = (mj0 > 0.f) ? acc[f][2] * 0.125f : -1e9f;
        acc[f][3] = (mj1 > 0.f) ? acc[f][3] * 0.125f : -1e9f;
        mx0 = fmaxf(mx0, fmaxf(acc[f][0], acc[f][1]));
        mx1 = fmaxf(mx1, fmaxf(acc[f][2], acc[f][3]));
    }
    mx0 = fmaxf(mx0, __shfl_xor_sync(0xffffffffu, mx0, 1));
    mx0 = fmaxf(mx0, __shfl_xor_sync(0xffffffffu, mx0, 2));
    mx1 = fmaxf(mx1, __shfl_xor_sync(0xffffffffu, mx1, 1));
    mx1 = fmaxf(mx1, __shfl_xor_sync(0xffffffffu, mx1, 2));

    float s0 = 0.f, s1 = 0.f;
    #pragma unroll
    for (int f = 0; f < 16; f++) {
        acc[f][0] = __expf(acc[f][0] - mx0);
        acc[f][1] = __expf(acc[f][1] - mx0);
        acc[f][2] = __expf(acc[f][2] - mx1);
        acc[f][3] = __expf(acc[f][3] - mx1);
        s0 += acc[f][0] + acc[f][1];
        s1 += acc[f][2] + acc[f][3];
    }
    s0 += __shfl_xor_sync(0xffffffffu, s0, 1);
    s0 += __shfl_xor_sync(0xffffffffu, s0, 2);
    s1 += __shfl_xor_sync(0xffffffffu, s1, 1);
    s1 += __shfl_xor_sync(0xffffffffu, s1, 2);

    // ---- pack P hi/lo into A-operand registers (C-frag == A-frag layout) ----
    uint32_t pAh[8][4], pAl[8][4];
    #pragma unroll
    for (int s = 0; s < 8; s++) {
        #pragma unroll
        for (int hf = 0; hf < 2; hf++) {
            const int f = 2 * s + hf;
            #pragma unroll
            for (int pr = 0; pr < 2; pr++) {
                const float x0 = acc[f][2 * pr], x1 = acc[f][2 * pr + 1];
                const __half h0 = __float2half_rn(x0), h1 = __float2half_rn(x1);
                const float r0f = __fsub_rn(x0, __half2float(h0));
                const float r1f = __fsub_rn(x1, __half2float(h1));
                __half2 hp = __halves2half2(h0, h1);
                __half2 lp = __halves2half2(__float2half_rn(r0f), __float2half_rn(r1f));
                pAh[s][hf * 2 + pr] = *(uint32_t*)&hp;
                pAl[s][hf * 2 + pr] = *(uint32_t*)&lp;
            }
        }
    }

    // ---- O^T[i][d] = P @ V^T; V [d][j] smem == col-major [k=j][n=d] ----
    float oc[8][4];
    #pragma unroll
    for (int t = 0; t < 8; t++)
        #pragma unroll
        for (int q = 0; q < 4; q++) oc[t][q] = 0.f;

    #pragma unroll
    for (int s = 0; s < 8; s++) {            // k = j, 16 per step
        #pragma unroll
        for (int dg = 0; dg < 4; dg++) {     // n = d, 16 per group
            uint32_t vh[4], vl[4];
            const uint32_t vaddr = smb + AT_VH +
                (uint32_t)((dg * 16 + l7 + kh * 8) * 272 + (s * 16 + mh * 8) * 2);
            ldsm_x4(vh, vaddr);
            ldsm_x4(vl, vaddr + (AT_VL - AT_VH));
            mma16816(oc[dg * 2],     pAh[s], vh);
            mma16816(oc[dg * 2],     pAl[s], vh);
            mma16816(oc[dg * 2],     pAh[s], vl);
            mma16816(oc[dg * 2 + 1], pAh[s], vh + 2);
            mma16816(oc[dg * 2 + 1], pAl[s], vh + 2);
            mma16816(oc[dg * 2 + 1], pAh[s], vl + 2);
        }
    }

    // ---- epilogue: /sum (register-local), exact GELU, fp16 store ----
    const float inv0 = 1.f / s0, inv1 = 1.f / s1;
    const int i0 = i0w + r_in;
    #pragma unroll
    for (int t = 0; t < 8; t++) {
        const int d = t * 8 + c_in;
        g_Bo[base + (size_t)d * SS + i0] =
            __float2half_rn(gelu_exact(oc[t][0] * inv0));
        g_Bo[base + (size_t)(d + 1) * SS + i0] =
            __float2half_rn(gelu_exact(oc[t][1] * inv0));
        g_Bo[base + (size_t)d * SS + i0 + 8] =
            __float2half_rn(gelu_exact(oc[t][2] * inv1));
        g_Bo[base + (size_t)(d + 1) * SS + i0 + 8] =
            __float2half_rn(gelu_exact(oc[t][3] * inv1));
    }
}

// ---------------------------------------------------------------------------
extern "C" void kernel_launch(void* const* d_in, const int* in_sizes, int n_in,
                              void* d_out, int out_size)
{
    const float* qk    = (const float*)d_in[0];
    const float* v     = (const float*)d_in[1];
    const float* masks = (const float*)d_in[2];
    const float* Wq    = (const float*)d_in[3];
    const float* bq    = (const float*)d_in[4];
    const float* Wk    = (const float*)d_in[5];
    const float* bk    = (const float*)d_in[6];
    const float* Wv    = (const float*)d_in[7];
    const float* bv    = (const float*)d_in[8];
    const float* Wo    = (const float*)d_in[9];
    const float* bo    = (const float*)d_in[10];
    float* out = (float*)d_out;

    __half *Bqk, *Bv, *Wqh, *Wkh, *Wvh, *Woh;
    cudaGetSymbolAddress((void**)&Bqk, g_Bqk);
    cudaGetSymbolAddress((void**)&Bv,  g_Bv);
    cudaGetSymbolAddress((void**)&Wqh, g_Wqh);
    cudaGetSymbolAddress((void**)&Wkh, g_Wkh);
    cudaGetSymbolAddress((void**)&Wvh, g_Wvh);
    cudaGetSymbolAddress((void**)&Woh, g_Woh);

    cudaFuncSetAttribute(gemm_qkv,
                         cudaFuncAttributeMaxDynamicSharedMemorySize, GSMEM_TOTAL);
    cudaFuncSetAttribute(gemm_out,
                         cudaFuncAttributeMaxDynamicSharedMemorySize, GSMEM_TOTAL);
    cudaFuncSetAttribute(attn_mma,
                         cudaFuncAttributeMaxDynamicSharedMemorySize, AT_SMEM);

    dim3 blk(256);

    // ---- conversions (merged: 2 launches) ----
    const int nW = DKK * DD / 4;               // 131072
    cvt_w4<<<4 * nW / 256, blk>>>((const float4*)Wq, (const float4*)Wk,
                                  (const float4*)Wv, (const float4*)Wo,
                                  (uint2*)Wqh, (uint2*)Wkh, (uint2*)Wvh, (uint2*)Woh);
    const int nX = NB * DD * SS / 4;
    cvt_x2<<<2 * nX / 256, blk>>>((const float4*)qk, (const float4*)v,
                                  (uint2*)Bqk, (uint2*)Bv, nX);

    // ---- merged Q/K/V projections (CTA 256x128, 6 y-blocks) ----
    gemm_qkv<<<dim3(32, 6, NB), blk, GSMEM_TOTAL>>>(bq, bk, bv);

    // ---- tensor-core attention + GELU (register-resident P) ----
    attn_mma<<<dim3(NWIN * NH, NB), blk, AT_SMEM>>>(masks);

    // ---- output projection + final mask (CTA 256x128) ----
    gemm_out<<<dim3(32, 4, NB), blk, GSMEM_TOTAL>>>(bo, masks, out);
}

// round 14
// speedup vs baseline: 1.2523x; 1.2523x over previous
#include <cuda_runtime.h>
#include <cuda_fp16.h>
#include <math.h>
#include <stdint.h>

#define NB   8
#define SS   4096
#define DD   1024
#define DKK  512
#define NH   8
#define WW   128
#define DH   64
#define NWIN 32   // S / W

// fp16 operand buffers (device globals: allowed)
__device__ __half g_Bqk[(size_t)NB * DD * SS];
__device__ __half g_Bv [(size_t)NB * DD * SS];
__device__ __half g_Bo [(size_t)NB * DKK * SS];
__device__ __half g_Qh[(size_t)NB * DKK * SS], g_Ql[(size_t)NB * DKK * SS];
__device__ __half g_Kh[(size_t)NB * DKK * SS], g_Kl[(size_t)NB * DKK * SS];
__device__ __half g_Vh[(size_t)NB * DKK * SS], g_Vl[(size_t)NB * DKK * SS];
__device__ __half g_Wqh[DKK * DD];
__device__ __half g_Wkh[DKK * DD];
__device__ __half g_Wvh[DKK * DD];
__device__ __half g_Woh[DD * DKK];

// ============================================================================
// PTX helpers (sm_80+ only — compute_103-safe)
// ============================================================================
__device__ __forceinline__ uint32_t smem_u32(const void* p) {
    uint32_t a;
    asm("{ .reg .u64 t; cvta.to.shared.u64 t, %1; cvt.u32.u64 %0, t; }"
        : "=r"(a) : "l"(p));
    return a;
}
__device__ __forceinline__ void ldsm_x4(uint32_t* r, uint32_t addr) {
    asm volatile("ldmatrix.sync.aligned.m8n8.x4.shared.b16 {%0,%1,%2,%3}, [%4];"
                 : "=r"(r[0]), "=r"(r[1]), "=r"(r[2]), "=r"(r[3]) : "r"(addr));
}
__device__ __forceinline__ void ldsm_x4_t(uint32_t* r, uint32_t addr) {
    asm volatile("ldmatrix.sync.aligned.m8n8.x4.trans.shared.b16 {%0,%1,%2,%3}, [%4];"
                 : "=r"(r[0]), "=r"(r[1]), "=r"(r[2]), "=r"(r[3]) : "r"(addr));
}
__device__ __forceinline__ void mma16816(float* d, const uint32_t* a, const uint32_t* b) {
    asm volatile(
        "mma.sync.aligned.m16n8k16.row.col.f32.f16.f16.f32 "
        "{%0,%1,%2,%3},{%4,%5,%6,%7},{%8,%9},{%0,%1,%2,%3};"
        : "+f"(d[0]), "+f"(d[1]), "+f"(d[2]), "+f"(d[3])
        : "r"(a[0]), "r"(a[1]), "r"(a[2]), "r"(a[3]), "r"(b[0]), "r"(b[1]));
}
__device__ __forceinline__ void cp_async16(uint32_t dst, const void* src) {
    asm volatile("cp.async.cg.shared.global [%0], [%1], 16;" :: "r"(dst), "l"(src));
}
__device__ __forceinline__ void cp_commit() {
    asm volatile("cp.async.commit_group;" ::: "memory");
}
template<int N> __device__ __forceinline__ void cp_wait() {
    asm volatile("cp.async.wait_group %0;" :: "n"(N) : "memory");
}
__device__ __forceinline__ float gelu_exact(float x) { return x * normcdff(x); }

// ============================================================================
// Conversion kernels (merged)
// ============================================================================
__global__ void cvt_w4(const float4* __restrict__ s0, const float4* __restrict__ s1,
                       const float4* __restrict__ s2, const float4* __restrict__ s3,
                       uint2* __restrict__ d0, uint2* __restrict__ d1,
                       uint2* __restrict__ d2, uint2* __restrict__ d3)
{
    int i = blockIdx.x * blockDim.x + threadIdx.x;   // 4 * 131072 total
    int w = i >> 17, j = i & 131071;
    const float4* s = (w == 0) ? s0 : (w == 1) ? s1 : (w == 2) ? s2 : s3;
    uint2* d = (w == 0) ? d0 : (w == 1) ? d1 : (w == 2) ? d2 : d3;
    float4 v = s[j];
    unsigned h0 = __half_as_ushort(__float2half_rn(v.x));
    unsigned h1 = __half_as_ushort(__float2half_rn(v.y));
    unsigned h2 = __half_as_ushort(__float2half_rn(v.z));
    unsigned h3 = __half_as_ushort(__float2half_rn(v.w));
    d[j] = make_uint2(h0 | (h1 << 16), h2 | (h3 << 16));
}

__global__ void cvt_x2(const float4* __restrict__ s0, const float4* __restrict__ s1,
                       uint2* __restrict__ d0, uint2* __restrict__ d1, int n4)
{
    int i = blockIdx.x * blockDim.x + threadIdx.x;   // 2 * n4 total
    int w = (i >= n4), j = w ? (i - n4) : i;
    const float4* s = w ? s1 : s0;
    uint2* d = w ? d1 : d0;
    float4 v = s[j];
    unsigned h0 = __half_as_ushort(__float2half_rn(v.x));
    unsigned h1 = __half_as_ushort(__float2half_rn(v.y));
    unsigned h2 = __half_as_ushort(__float2half_rn(v.z));
    unsigned h3 = __half_as_ushort(__float2half_rn(v.w));
    d[j] = make_uint2(h0 | (h1 << 16), h2 | (h3 << 16));
}

// ============================================================================
// GEMM smem layout (R11-proven: CTA 128x128, K-chunk 32, 3 stages)
// ============================================================================
#define OFF_AH   0
#define OFF_BH   10240
#define STAGE_SZ 18944
#define NSTAGE   3
#define GSMEM_TOTAL (NSTAGE * STAGE_SZ)

// ============================================================================
// Merged QKV GEMM: grid (32, 12, NB). by>>2 selects Q/K/V segment.
// C = W @ B[bz] + bias, written as fp16 hi/lo.  (R11-proven)
// ============================================================================
__global__ __launch_bounds__(256, 2) void gemm_qkv(
    const float* __restrict__ bq, const float* __restrict__ bk,
    const float* __restrict__ bv)
{
    extern __shared__ char sm[];
    const int tid  = threadIdx.x;
    const int warp = tid >> 5;
    const int lane = tid & 31;
    const int bx = blockIdx.x, by = blockIdx.y, bz = blockIdx.z;
    const int seg = by >> 2, byy = by & 3;
    const int n0 = bx * 128, m0 = byy * 128;
    const int wm = (warp >> 1) * 32;
    const int wn = (warp & 1) * 64;
    const int M = DKK, N = SS, K = DD;

    const __half* Ah  = (seg == 0) ? g_Wqh : (seg == 1) ? g_Wkh : g_Wvh;
    const __half* Bgl = (seg == 2) ? g_Bv : g_Bqk;
    const float* bias = (seg == 0) ? bq : (seg == 1) ? bk : bv;
    __half* Ch = ((seg == 0) ? g_Qh : (seg == 1) ? g_Kh : g_Vh) + (size_t)bz * M * N;
    __half* Cl = ((seg == 0) ? g_Ql : (seg == 1) ? g_Kl : g_Vl) + (size_t)bz * M * N;

    const __half* Bb = Bgl + (size_t)bz * K * N;
    const uint32_t smb = smem_u32(sm);

    const int ar = tid >> 2, aq = tid & 3;
    const int br = tid >> 4, bq2 = tid & 15;

    auto issue = [&](int c, int st) {
        const uint32_t sb = smb + st * STAGE_SZ;
        const __half* Ahp = Ah + (size_t)m0 * K + c * 32;
        const __half* Bp  = Bb + (size_t)(c * 32) * N + n0;
        #pragma unroll
        for (int it = 0; it < 2; it++) {
            int r = ar + it * 64;
            cp_async16(sb + OFF_AH + (uint32_t)(r * 80 + aq * 16),
                       Ahp + (size_t)r * K + aq * 8);
            int rb = br + it * 16;
            cp_async16(sb + OFF_BH + (uint32_t)(rb * 272 + bq2 * 16),
                       Bp + (size_t)rb * N + bq2 * 8);
        }
    };

    float acc[2][8][4];
    #pragma unroll
    for (int i = 0; i < 2; i++)
        #pragma unroll
        for (int j = 0; j < 8; j++)
            #pragma unroll
            for (int t = 0; t < 4; t++) acc[i][j][t] = 0.f;

    const int nch = K >> 5;
    issue(0, 0); cp_commit();
    issue(1, 1); cp_commit();

    const int lrow16 = lane & 15;
    const int khalf  = (lane >> 4) * 8;
    const uint32_t l7 = lane & 7, mh = (lane >> 3) & 1, kh = (lane >> 4) & 1;

    for (int c = 0; c < nch; c++) {
        cp_wait<1>();
        __syncthreads();
        if (c + 2 < nch) issue(c + 2, (c + 2) % NSTAGE);
        cp_commit();

        const uint32_t bb = smb + (c % NSTAGE) * STAGE_SZ;
        #pragma unroll
        for (int s = 0; s < 2; s++) {
            const int ks = s * 16;
            uint32_t bh[4][4];
            const uint32_t brow = (uint32_t)((ks + mh * 8 + l7) * 272);
            #pragma unroll
            for (int nj = 0; nj < 4; nj++)
                ldsm_x4_t(bh[nj], bb + OFF_BH + brow +
                          (uint32_t)((wn + nj * 16 + kh * 8) * 2));
            #pragma unroll
            for (int mi = 0; mi < 2; mi++) {
                uint32_t ah[4];
                const uint32_t aoff =
                    (uint32_t)((wm + mi * 16 + lrow16) * 80 + (ks + khalf) * 2);
                ldsm_x4(ah, bb + OFF_AH + aoff);
                #pragma unroll
                for (int nj = 0; nj < 4; nj++) {
                    mma16816(acc[mi][nj * 2],     ah, bh[nj]);
                    mma16816(acc[mi][nj * 2 + 1], ah, bh[nj] + 2);
                }
            }
        }
    }

    const int r_in = lane >> 2;
    const int c_in = (lane & 3) * 2;
    #pragma unroll
    for (int mi = 0; mi < 2; mi++) {
        const int r0 = m0 + wm + mi * 16 + r_in;
        const float b0 = bias[r0];
        const float b1 = bias[r0 + 8];
        #pragma unroll
        for (int ni = 0; ni < 8; ni++) {
            const int col = n0 + wn + ni * 8 + c_in;
            float v0 = acc[mi][ni][0] + b0, v1 = acc[mi][ni][1] + b0;
            float v2 = acc[mi][ni][2] + b1, v3 = acc[mi][ni][3] + b1;
            __half h0 = __float2half_rn(v0), h1 = __float2half_rn(v1);
            __half h2 = __float2half_rn(v2), h3 = __float2half_rn(v3);
            __half l0 = __float2half_rn(__fsub_rn(v0, __half2float(h0)));
            __half l1 = __float2half_rn(__fsub_rn(v1, __half2float(h1)));
            __half l2 = __float2half_rn(__fsub_rn(v2, __half2float(h2)));
            __half l3 = __float2half_rn(__fsub_rn(v3, __half2float(h3)));
            *(__half2*)(Ch + (size_t)r0 * N + col)       = __halves2half2(h0, h1);
            *(__half2*)(Cl + (size_t)r0 * N + col)       = __halves2half2(l0, l1);
            *(__half2*)(Ch + (size_t)(r0 + 8) * N + col) = __halves2half2(h2, h3);
            *(__half2*)(Cl + (size_t)(r0 + 8) * N + col) = __halves2half2(l2, l3);
        }
    }
}

// ============================================================================
// Final projection GEMM: fp32 out with column mask.  (R11-proven)
// ============================================================================
__global__ __launch_bounds__(256, 2) void gemm_out(
    const float* __restrict__ bias, const float* __restrict__ cmask,
    float* __restrict__ C)
{
    extern __shared__ char sm[];
    const int tid  = threadIdx.x;
    const int warp = tid >> 5;
    const int lane = tid & 31;
    const int bx = blockIdx.x, by = blockIdx.y, bz = blockIdx.z;
    const int n0 = bx * 128, m0 = by * 128;
    const int wm = (warp >> 1) * 32;
    const int wn = (warp & 1) * 64;
    const int M = DD, N = SS, K = DKK;

    const __half* Bb = g_Bo + (size_t)bz * K * N;
    const uint32_t smb = smem_u32(sm);

    const int ar = tid >> 2, aq = tid & 3;
    const int br = tid >> 4, bq2 = tid & 15;

    auto issue = [&](int c, int st) {
        const uint32_t sb = smb + st * STAGE_SZ;
        const __half* Ahp = g_Woh + (size_t)m0 * K + c * 32;
        const __half* Bp  = Bb + (size_t)(c * 32) * N + n0;
        #pragma unroll
        for (int it = 0; it < 2; it++) {
            int r = ar + it * 64;
            cp_async16(sb + OFF_AH + (uint32_t)(r * 80 + aq * 16),
                       Ahp + (size_t)r * K + aq * 8);
            int rb = br + it * 16;
            cp_async16(sb + OFF_BH + (uint32_t)(rb * 272 + bq2 * 16),
                       Bp + (size_t)rb * N + bq2 * 8);
        }
    };

    float acc[2][8][4];
    #pragma unroll
    for (int i = 0; i < 2; i++)
        #pragma unroll
        for (int j = 0; j < 8; j++)
            #pragma unroll
            for (int t = 0; t < 4; t++) acc[i][j][t] = 0.f;

    const int nch = K >> 5;
    issue(0, 0); cp_commit();
    issue(1, 1); cp_commit();

    const int lrow16 = lane & 15;
    const int khalf  = (lane >> 4) * 8;
    const uint32_t l7 = lane & 7, mh = (lane >> 3) & 1, kh = (lane >> 4) & 1;

    for (int c = 0; c < nch; c++) {
        cp_wait<1>();
        __syncthreads();
        if (c + 2 < nch) issue(c + 2, (c + 2) % NSTAGE);
        cp_commit();

        const uint32_t bb = smb + (c % NSTAGE) * STAGE_SZ;
        #pragma unroll
        for (int s = 0; s < 2; s++) {
            const int ks = s * 16;
            uint32_t bh[4][4];
            const uint32_t brow = (uint32_t)((ks + mh * 8 + l7) * 272);
            #pragma unroll
            for (int nj = 0; nj < 4; nj++)
                ldsm_x4_t(bh[nj], bb + OFF_BH + brow +
                          (uint32_t)((wn + nj * 16 + kh * 8) * 2));
            #pragma unroll
            for (int mi = 0; mi < 2; mi++) {
                uint32_t ah[4];
                const uint32_t aoff =
                    (uint32_t)((wm + mi * 16 + lrow16) * 80 + (ks + khalf) * 2);
                ldsm_x4(ah, bb + OFF_AH + aoff);
                #pragma unroll
                for (int nj = 0; nj < 4; nj++) {
                    mma16816(acc[mi][nj * 2],     ah, bh[nj]);
                    mma16816(acc[mi][nj * 2 + 1], ah, bh[nj] + 2);
                }
            }
        }
    }

    const int r_in = lane >> 2;
    const int c_in = (lane & 3) * 2;
    float* Cb = C + (size_t)bz * M * N;
    #pragma unroll
    for (int mi = 0; mi < 2; mi++) {
        const int r0 = m0 + wm + mi * 16 + r_in;
        const float b0 = bias[r0];
        const float b1 = bias[r0 + 8];
        #pragma unroll
        for (int ni = 0; ni < 8; ni++) {
            const int col = n0 + wn + ni * 8 + c_in;
            float m0f = cmask[(size_t)bz * N + col];
            float m1f = cmask[(size_t)bz * N + col + 1];
            *(float2*)(Cb + (size_t)r0 * N + col) =
                make_float2((acc[mi][ni][0] + b0) * m0f, (acc[mi][ni][1] + b0) * m1f);
            *(float2*)(Cb + (size_t)(r0 + 8) * N + col) =
                make_float2((acc[mi][ni][2] + b1) * m0f, (acc[mi][ni][3] + b1) * m1f);
        }
    }
}

// ============================================================================
// Tensor-core windowed attention, register-resident P.
// R13 change: P is fp16-rn ONLY in AV (drop P-lo pass): O = P@Vh + P@Vl.
// QK^T keeps all 3 hi/lo passes. Saves 1/3 of AV MMAs + 32 regs (pAl bank).
// ============================================================================
#define AT_QH  0
#define AT_QL  17408
#define AT_KH  34816
#define AT_KL  52224
#define AT_VH  69632
#define AT_VL  87040
#define AT_MSK 104448   // float[128]
#define AT_SMEM 104960

__global__ __launch_bounds__(256, 2) void attn_mma(const float* __restrict__ masks)
{
    extern __shared__ char sm[];
    const uint32_t smb = smem_u32(sm);
    const int tid = threadIdx.x, warp = tid >> 5, lane = tid & 31;
    const int wh = blockIdx.x, w = wh >> 3, h = wh & 7, b = blockIdx.y;
    const size_t base = ((size_t)b * DKK + h * 64) * SS + (size_t)w * WW;

    {
        const __half* srcs[6] = { g_Qh + base, g_Ql + base, g_Kh + base,
                                  g_Kl + base, g_Vh + base, g_Vl + base };
        #pragma unroll
        for (int t = 0; t < 6; t++) {
            const uint32_t dstb = smb + t * 17408;
            #pragma unroll
            for (int it = 0; it < 4; it++) {
                int idx = tid + it * 256;
                int row = idx >> 4, ch = idx & 15;
                cp_async16(dstb + row * 272 + ch * 16,
                           srcs[t] + (size_t)row * SS + ch * 8);
            }
        }
        cp_commit();
    }
    if (tid < 32) {
        float4 mv = *(const float4*)(masks + (size_t)b * SS + w * WW + tid * 4);
        *(float4*)(sm + AT_MSK + tid * 16) = mv;
    }
    cp_wait<0>();
    __syncthreads();

    const int r_in = lane >> 2, c_in = (lane & 3) * 2;
    const uint32_t l7 = lane & 7, mh = (lane >> 3) & 1, kh = (lane >> 4) & 1;
    const int i0w = warp * 16;

    // ---- QK^T (3-pass hi/lo) ----
    float acc[16][4];
    #pragma unroll
    for (int f = 0; f < 16; f++)
        #pragma unroll
        for (int t = 0; t < 4; t++) acc[f][t] = 0.f;

    #pragma unroll
    for (int s = 0; s < 4; s++) {
        uint32_t ah[4], al[4];
        const uint32_t aaddr = smb + (s * 16 + kh * 8 + l7) * 272 + (i0w + mh * 8) * 2;
        ldsm_x4_t(ah, aaddr + AT_QH);
        ldsm_x4_t(al, aaddr + AT_QL);
        #pragma unroll
        for (int q = 0; q < 8; q++) {
            const uint32_t baddr = smb + AT_KH +
                (s * 16 + mh * 8 + l7) * 272 + (q * 16 + kh * 8) * 2;
            uint32_t bh4[4], bl4[4];
            ldsm_x4_t(bh4, baddr);
            ldsm_x4_t(bl4, baddr + (AT_KL - AT_KH));
            const int f0 = q * 2;
            mma16816(acc[f0],     ah, bh4);
            mma16816(acc[f0],     al, bh4);
            mma16816(acc[f0],     ah, bl4);
            mma16816(acc[f0 + 1], ah, bh4 + 2);
            mma16816(acc[f0 + 1], al, bh4 + 2);
            mma16816(acc[f0 + 1], ah, bl4 + 2);
        }
    }

    // ---- mask + scale + warp-local softmax ----
    const float* mk = (const float*)(sm + AT_MSK);
    float mx0 = -1e30f, mx1 = -1e30f;
    #pragma unroll
    for (int f = 0; f < 16; f++) {
        const int j = f * 8 + c_in;
        const float mj0 = mk[j], mj1 = mk[j + 1];
        acc[f][0] = (mj0 > 0.f) ? acc[f][0] * 0.125f : -1e9f;
        acc[f][1] = (mj1 > 0.f) ? acc[f][1] * 0.125f : -1e9f;
        acc[f][2] = (mj0 > 0.f) ? acc[f][2] * 0.125f : -1e9f;
        acc[f][3] = (mj1 > 0.f) ? acc[f][3] * 0.125f : -1e9f;
        mx0 = fmaxf(mx0, fmaxf(acc[f][0], acc[f][1]));
        mx1 = fmaxf(mx1, fmaxf(acc[f][2], acc[f][3]));
    }
    mx0 = fmaxf(mx0, __shfl_xor_sync(0xffffffffu, mx0, 1));
    mx0 = fmaxf(mx0, __shfl_xor_sync(0xffffffffu, mx0, 2));
    mx1 = fmaxf(mx1, __shfl_xor_sync(0xffffffffu, mx1, 1));
    mx1 = fmaxf(mx1, __shfl_xor_sync(0xffffffffu, mx1, 2));

    float s0 = 0.f, s1 = 0.f;
    #pragma unroll
    for (int f = 0; f < 16; f++) {
        acc[f][0] = __expf(acc[f][0] - mx0);
        acc[f][1] = __expf(acc[f][1] - mx0);
        acc[f][2] = __expf(acc[f][2] - mx1);
        acc[f][3] = __expf(acc[f][3] - mx1);
        s0 += acc[f][0] + acc[f][1];
        s1 += acc[f][2] + acc[f][3];
    }
    s0 += __shfl_xor_sync(0xffffffffu, s0, 1);
    s0 += __shfl_xor_sync(0xffffffffu, s0, 2);
    s1 += __shfl_xor_sync(0xffffffffu, s1, 1);
    s1 += __shfl_xor_sync(0xffffffffu, s1, 2);

    // ---- pack P (fp16-rn only) into A-operand registers ----
    uint32_t pAh[8][4];
    #pragma unroll
    for (int s = 0; s < 8; s++) {
        #pragma unroll
        for (int hf = 0; hf < 2; hf++) {
            const int f = 2 * s + hf;
            #pragma unroll
            for (int pr = 0; pr < 2; pr++) {
                __half2 hp = __halves2half2(__float2half_rn(acc[f][2 * pr]),
                                            __float2half_rn(acc[f][2 * pr + 1]));
                pAh[s][hf * 2 + pr] = *(uint32_t*)&hp;
            }
        }
    }

    // ---- O^T[i][d] = P @ (Vh + Vl)^T ----
    float oc[8][4];
    #pragma unroll
    for (int t = 0; t < 8; t++)
        #pragma unroll
        for (int q = 0; q < 4; q++) oc[t][q] = 0.f;

    #pragma unroll
    for (int s = 0; s < 8; s++) {            // k = j, 16 per step
        #pragma unroll
        for (int dg = 0; dg < 4; dg++) {     // n = d, 16 per group
            uint32_t vh[4], vl[4];
            const uint32_t vaddr = smb + AT_VH +
                (uint32_t)((dg * 16 + l7 + kh * 8) * 272 + (s * 16 + mh * 8) * 2);
            ldsm_x4(vh, vaddr);
            ldsm_x4(vl, vaddr + (AT_VL - AT_VH));
            mma16816(oc[dg * 2],     pAh[s], vh);
            mma16816(oc[dg * 2],     pAh[s], vl);
            mma16816(oc[dg * 2 + 1], pAh[s], vh + 2);
            mma16816(oc[dg * 2 + 1], pAh[s], vl + 2);
        }
    }

    // ---- epilogue: /sum (register-local), exact GELU, fp16 store ----
    const float inv0 = 1.f / s0, inv1 = 1.f / s1;
    const int i0 = i0w + r_in;
    #pragma unroll
    for (int t = 0; t < 8; t++) {
        const int d = t * 8 + c_in;
        g_Bo[base + (size_t)d * SS + i0] =
            __float2half_rn(gelu_exact(oc[t][0] * inv0));
        g_Bo[base + (size_t)(d + 1) * SS + i0] =
            __float2half_rn(gelu_exact(oc[t][1] * inv0));
        g_Bo[base + (size_t)d * SS + i0 + 8] =
            __float2half_rn(gelu_exact(oc[t][2] * inv1));
        g_Bo[base + (size_t)(d + 1) * SS + i0 + 8] =
            __float2half_rn(gelu_exact(oc[t][3] * inv1));
    }
}

// ---------------------------------------------------------------------------
extern "C" void kernel_launch(void* const* d_in, const int* in_sizes, int n_in,
                              void* d_out, int out_size)
{
    const float* qk    = (const float*)d_in[0];
    const float* v     = (const float*)d_in[1];
    const float* masks = (const float*)d_in[2];
    const float* Wq    = (const float*)d_in[3];
    const float* bq    = (const float*)d_in[4];
    const float* Wk    = (const float*)d_in[5];
    const float* bk    = (const float*)d_in[6];
    const float* Wv    = (const float*)d_in[7];
    const float* bv    = (const float*)d_in[8];
    const float* Wo    = (const float*)d_in[9];
    const float* bo    = (const float*)d_in[10];
    float* out = (float*)d_out;

    __half *Bqk, *Bv, *Wqh, *Wkh, *Wvh, *Woh;
    cudaGetSymbolAddress((void**)&Bqk, g_Bqk);
    cudaGetSymbolAddress((void**)&Bv,  g_Bv);
    cudaGetSymbolAddress((void**)&Wqh, g_Wqh);
    cudaGetSymbolAddress((void**)&Wkh, g_Wkh);
    cudaGetSymbolAddress((void**)&Wvh, g_Wvh);
    cudaGetSymbolAddress((void**)&Woh, g_Woh);

    cudaFuncSetAttribute(gemm_qkv,
                         cudaFuncAttributeMaxDynamicSharedMemorySize, GSMEM_TOTAL);
    cudaFuncSetAttribute(gemm_out,
                         cudaFuncAttributeMaxDynamicSharedMemorySize, GSMEM_TOTAL);
    cudaFuncSetAttribute(attn_mma,
                         cudaFuncAttributeMaxDynamicSharedMemorySize, AT_SMEM);

    dim3 blk(256);

    // ---- conversions (merged: 2 launches) ----
    const int nW = DKK * DD / 4;               // 131072
    cvt_w4<<<4 * nW / 256, blk>>>((const float4*)Wq, (const float4*)Wk,
                                  (const float4*)Wv, (const float4*)Wo,
                                  (uint2*)Wqh, (uint2*)Wkh, (uint2*)Wvh, (uint2*)Woh);
    const int nX = NB * DD * SS / 4;
    cvt_x2<<<2 * nX / 256, blk>>>((const float4*)qk, (const float4*)v,
                                  (uint2*)Bqk, (uint2*)Bv, nX);

    // ---- merged Q/K/V projections (single launch, 12 y-blocks) ----
    gemm_qkv<<<dim3(32, 12, NB), blk, GSMEM_TOTAL>>>(bq, bk, bv);

    // ---- tensor-core attention + GELU (register-resident P, fp16 P) ----
    attn_mma<<<dim3(NWIN * NH, NB), blk, AT_SMEM>>>(masks);

    // ---- output projection + final mask ----
    gemm_out<<<dim3(32, 8, NB), blk, GSMEM_TOTAL>>>(bo, masks, out);
}

// round 15
// speedup vs baseline: 1.2546x; 1.0019x over previous
#include <cuda_runtime.h>
#include <cuda_fp16.h>
#include <math.h>
#include <stdint.h>

#define NB   8
#define SS   4096
#define DD   1024
#define DKK  512
#define NH   8
#define WW   128
#define DH   64
#define NWIN 32   // S / W

// fp16 operand buffers (device globals: allowed)
__device__ __half g_Bqk[(size_t)NB * DD * SS];
__device__ __half g_Bv [(size_t)NB * DD * SS];
__device__ __half g_Bo [(size_t)NB * DKK * SS];
__device__ __half g_Qh[(size_t)NB * DKK * SS], g_Ql[(size_t)NB * DKK * SS];
__device__ __half g_Kh[(size_t)NB * DKK * SS], g_Kl[(size_t)NB * DKK * SS];
__device__ __half g_Vh[(size_t)NB * DKK * SS], g_Vl[(size_t)NB * DKK * SS];
__device__ __half g_Wqh[DKK * DD];
__device__ __half g_Wkh[DKK * DD];
__device__ __half g_Wvh[DKK * DD];
__device__ __half g_Woh[DD * DKK];

// ============================================================================
// PTX helpers (sm_80+ only — compute_103-safe)
// ============================================================================
__device__ __forceinline__ uint32_t smem_u32(const void* p) {
    uint32_t a;
    asm("{ .reg .u64 t; cvta.to.shared.u64 t, %1; cvt.u32.u64 %0, t; }"
        : "=r"(a) : "l"(p));
    return a;
}
__device__ __forceinline__ void ldsm_x4(uint32_t* r, uint32_t addr) {
    asm volatile("ldmatrix.sync.aligned.m8n8.x4.shared.b16 {%0,%1,%2,%3}, [%4];"
                 : "=r"(r[0]), "=r"(r[1]), "=r"(r[2]), "=r"(r[3]) : "r"(addr));
}
__device__ __forceinline__ void ldsm_x4_t(uint32_t* r, uint32_t addr) {
    asm volatile("ldmatrix.sync.aligned.m8n8.x4.trans.shared.b16 {%0,%1,%2,%3}, [%4];"
                 : "=r"(r[0]), "=r"(r[1]), "=r"(r[2]), "=r"(r[3]) : "r"(addr));
}
__device__ __forceinline__ void mma16816(float* d, const uint32_t* a, const uint32_t* b) {
    asm volatile(
        "mma.sync.aligned.m16n8k16.row.col.f32.f16.f16.f32 "
        "{%0,%1,%2,%3},{%4,%5,%6,%7},{%8,%9},{%0,%1,%2,%3};"
        : "+f"(d[0]), "+f"(d[1]), "+f"(d[2]), "+f"(d[3])
        : "r"(a[0]), "r"(a[1]), "r"(a[2]), "r"(a[3]), "r"(b[0]), "r"(b[1]));
}
__device__ __forceinline__ void cp_async16(uint32_t dst, const void* src) {
    asm volatile("cp.async.cg.shared.global [%0], [%1], 16;" :: "r"(dst), "l"(src));
}
__device__ __forceinline__ void cp_commit() {
    asm volatile("cp.async.commit_group;" ::: "memory");
}
template<int N> __device__ __forceinline__ void cp_wait() {
    asm volatile("cp.async.wait_group %0;" :: "n"(N) : "memory");
}
__device__ __forceinline__ float gelu_exact(float x) { return x * normcdff(x); }

// ============================================================================
// Conversion kernels (merged)
// ============================================================================
__global__ void cvt_w4(const float4* __restrict__ s0, const float4* __restrict__ s1,
                       const float4* __restrict__ s2, const float4* __restrict__ s3,
                       uint2* __restrict__ d0, uint2* __restrict__ d1,
                       uint2* __restrict__ d2, uint2* __restrict__ d3)
{
    int i = blockIdx.x * blockDim.x + threadIdx.x;   // 4 * 131072 total
    int w = i >> 17, j = i & 131071;
    const float4* s = (w == 0) ? s0 : (w == 1) ? s1 : (w == 2) ? s2 : s3;
    uint2* d = (w == 0) ? d0 : (w == 1) ? d1 : (w == 2) ? d2 : d3;
    float4 v = s[j];
    unsigned h0 = __half_as_ushort(__float2half_rn(v.x));
    unsigned h1 = __half_as_ushort(__float2half_rn(v.y));
    unsigned h2 = __half_as_ushort(__float2half_rn(v.z));
    unsigned h3 = __half_as_ushort(__float2half_rn(v.w));
    d[j] = make_uint2(h0 | (h1 << 16), h2 | (h3 << 16));
}

__global__ void cvt_x2(const float4* __restrict__ s0, const float4* __restrict__ s1,
                       uint2* __restrict__ d0, uint2* __restrict__ d1, int n4)
{
    int i = blockIdx.x * blockDim.x + threadIdx.x;   // 2 * n4 total
    int w = (i >= n4), j = w ? (i - n4) : i;
    const float4* s = w ? s1 : s0;
    uint2* d = w ? d1 : d0;
    float4 v = s[j];
    unsigned h0 = __half_as_ushort(__float2half_rn(v.x));
    unsigned h1 = __half_as_ushort(__float2half_rn(v.y));
    unsigned h2 = __half_as_ushort(__float2half_rn(v.z));
    unsigned h3 = __half_as_ushort(__float2half_rn(v.w));
    d[j] = make_uint2(h0 | (h1 << 16), h2 | (h3 << 16));
}

// ============================================================================
// GEMM smem layout: CTA 128x128, K-chunk 32, 4 stages (deeper prefetch)
// ============================================================================
#define OFF_AH   0
#define OFF_BH   10240
#define STAGE_SZ 18944
#define NSTAGE   4
#define GSMEM_TOTAL (NSTAGE * STAGE_SZ)

// ============================================================================
// Merged QKV GEMM: grid (32, 12, NB). by>>2 selects Q/K/V segment.
// C = W @ B[bz] + bias, written as fp16 hi/lo (V: hi only — Vl is dead).
// ============================================================================
__global__ __launch_bounds__(256, 2) void gemm_qkv(
    const float* __restrict__ bq, const float* __restrict__ bk,
    const float* __restrict__ bv)
{
    extern __shared__ char sm[];
    const int tid  = threadIdx.x;
    const int warp = tid >> 5;
    const int lane = tid & 31;
    const int bx = blockIdx.x, by = blockIdx.y, bz = blockIdx.z;
    const int seg = by >> 2, byy = by & 3;
    const int n0 = bx * 128, m0 = byy * 128;
    const int wm = (warp >> 1) * 32;
    const int wn = (warp & 1) * 64;
    const int M = DKK, N = SS, K = DD;

    const __half* Ah  = (seg == 0) ? g_Wqh : (seg == 1) ? g_Wkh : g_Wvh;
    const __half* Bgl = (seg == 2) ? g_Bv : g_Bqk;
    const float* bias = (seg == 0) ? bq : (seg == 1) ? bk : bv;
    __half* Ch = ((seg == 0) ? g_Qh : (seg == 1) ? g_Kh : g_Vh) + (size_t)bz * M * N;
    __half* Cl = ((seg == 0) ? g_Ql : (seg == 1) ? g_Kl : g_Vl) + (size_t)bz * M * N;
    const bool writeCl = (seg != 2);   // Vl never consumed (AV uses Vh only)

    const __half* Bb = Bgl + (size_t)bz * K * N;
    const uint32_t smb = smem_u32(sm);

    const int ar = tid >> 2, aq = tid & 3;
    const int br = tid >> 4, bq2 = tid & 15;

    auto issue = [&](int c, int st) {
        const uint32_t sb = smb + st * STAGE_SZ;
        const __half* Ahp = Ah + (size_t)m0 * K + c * 32;
        const __half* Bp  = Bb + (size_t)(c * 32) * N + n0;
        #pragma unroll
        for (int it = 0; it < 2; it++) {
            int r = ar + it * 64;
            cp_async16(sb + OFF_AH + (uint32_t)(r * 80 + aq * 16),
                       Ahp + (size_t)r * K + aq * 8);
            int rb = br + it * 16;
            cp_async16(sb + OFF_BH + (uint32_t)(rb * 272 + bq2 * 16),
                       Bp + (size_t)rb * N + bq2 * 8);
        }
    };

    float acc[2][8][4];
    #pragma unroll
    for (int i = 0; i < 2; i++)
        #pragma unroll
        for (int j = 0; j < 8; j++)
            #pragma unroll
            for (int t = 0; t < 4; t++) acc[i][j][t] = 0.f;

    const int nch = K >> 5;
    issue(0, 0); cp_commit();
    issue(1, 1); cp_commit();
    issue(2, 2); cp_commit();

    const int lrow16 = lane & 15;
    const int khalf  = (lane >> 4) * 8;
    const uint32_t l7 = lane & 7, mh = (lane >> 3) & 1, kh = (lane >> 4) & 1;

    for (int c = 0; c < nch; c++) {
        cp_wait<2>();
        __syncthreads();
        if (c + 3 < nch) issue(c + 3, (c + 3) % NSTAGE);
        cp_commit();

        const uint32_t bb = smb + (c % NSTAGE) * STAGE_SZ;
        #pragma unroll
        for (int s = 0; s < 2; s++) {
            const int ks = s * 16;
            uint32_t bh[4][4];
            const uint32_t brow = (uint32_t)((ks + mh * 8 + l7) * 272);
            #pragma unroll
            for (int nj = 0; nj < 4; nj++)
                ldsm_x4_t(bh[nj], bb + OFF_BH + brow +
                          (uint32_t)((wn + nj * 16 + kh * 8) * 2));
            #pragma unroll
            for (int mi = 0; mi < 2; mi++) {
                uint32_t ah[4];
                const uint32_t aoff =
                    (uint32_t)((wm + mi * 16 + lrow16) * 80 + (ks + khalf) * 2);
                ldsm_x4(ah, bb + OFF_AH + aoff);
                #pragma unroll
                for (int nj = 0; nj < 4; nj++) {
                    mma16816(acc[mi][nj * 2],     ah, bh[nj]);
                    mma16816(acc[mi][nj * 2 + 1], ah, bh[nj] + 2);
                }
            }
        }
    }

    const int r_in = lane >> 2;
    const int c_in = (lane & 3) * 2;
    #pragma unroll
    for (int mi = 0; mi < 2; mi++) {
        const int r0 = m0 + wm + mi * 16 + r_in;
        const float b0 = bias[r0];
        const float b1 = bias[r0 + 8];
        #pragma unroll
        for (int ni = 0; ni < 8; ni++) {
            const int col = n0 + wn + ni * 8 + c_in;
            float v0 = acc[mi][ni][0] + b0, v1 = acc[mi][ni][1] + b0;
            float v2 = acc[mi][ni][2] + b1, v3 = acc[mi][ni][3] + b1;
            __half h0 = __float2half_rn(v0), h1 = __float2half_rn(v1);
            __half h2 = __float2half_rn(v2), h3 = __float2half_rn(v3);
            *(__half2*)(Ch + (size_t)r0 * N + col)       = __halves2half2(h0, h1);
            *(__half2*)(Ch + (size_t)(r0 + 8) * N + col) = __halves2half2(h2, h3);
            if (writeCl) {
                __half l0 = __float2half_rn(__fsub_rn(v0, __half2float(h0)));
                __half l1 = __float2half_rn(__fsub_rn(v1, __half2float(h1)));
                __half l2 = __float2half_rn(__fsub_rn(v2, __half2float(h2)));
                __half l3 = __float2half_rn(__fsub_rn(v3, __half2float(h3)));
                *(__half2*)(Cl + (size_t)r0 * N + col)       = __halves2half2(l0, l1);
                *(__half2*)(Cl + (size_t)(r0 + 8) * N + col) = __halves2half2(l2, l3);
            }
        }
    }
}

// ============================================================================
// Final projection GEMM: fp32 out with column mask. (4-stage pipeline)
// ============================================================================
__global__ __launch_bounds__(256, 2) void gemm_out(
    const float* __restrict__ bias, const float* __restrict__ cmask,
    float* __restrict__ C)
{
    extern __shared__ char sm[];
    const int tid  = threadIdx.x;
    const int warp = tid >> 5;
    const int lane = tid & 31;
    const int bx = blockIdx.x, by = blockIdx.y, bz = blockIdx.z;
    const int n0 = bx * 128, m0 = by * 128;
    const int wm = (warp >> 1) * 32;
    const int wn = (warp & 1) * 64;
    const int M = DD, N = SS, K = DKK;

    const __half* Bb = g_Bo + (size_t)bz * K * N;
    const uint32_t smb = smem_u32(sm);

    const int ar = tid >> 2, aq = tid & 3;
    const int br = tid >> 4, bq2 = tid & 15;

    auto issue = [&](int c, int st) {
        const uint32_t sb = smb + st * STAGE_SZ;
        const __half* Ahp = g_Woh + (size_t)m0 * K + c * 32;
        const __half* Bp  = Bb + (size_t)(c * 32) * N + n0;
        #pragma unroll
        for (int it = 0; it < 2; it++) {
            int r = ar + it * 64;
            cp_async16(sb + OFF_AH + (uint32_t)(r * 80 + aq * 16),
                       Ahp + (size_t)r * K + aq * 8);
            int rb = br + it * 16;
            cp_async16(sb + OFF_BH + (uint32_t)(rb * 272 + bq2 * 16),
                       Bp + (size_t)rb * N + bq2 * 8);
        }
    };

    float acc[2][8][4];
    #pragma unroll
    for (int i = 0; i < 2; i++)
        #pragma unroll
        for (int j = 0; j < 8; j++)
            #pragma unroll
            for (int t = 0; t < 4; t++) acc[i][j][t] = 0.f;

    const int nch = K >> 5;
    issue(0, 0); cp_commit();
    issue(1, 1); cp_commit();
    issue(2, 2); cp_commit();

    const int lrow16 = lane & 15;
    const int khalf  = (lane >> 4) * 8;
    const uint32_t l7 = lane & 7, mh = (lane >> 3) & 1, kh = (lane >> 4) & 1;

    for (int c = 0; c < nch; c++) {
        cp_wait<2>();
        __syncthreads();
        if (c + 3 < nch) issue(c + 3, (c + 3) % NSTAGE);
        cp_commit();

        const uint32_t bb = smb + (c % NSTAGE) * STAGE_SZ;
        #pragma unroll
        for (int s = 0; s < 2; s++) {
            const int ks = s * 16;
            uint32_t bh[4][4];
            const uint32_t brow = (uint32_t)((ks + mh * 8 + l7) * 272);
            #pragma unroll
            for (int nj = 0; nj < 4; nj++)
                ldsm_x4_t(bh[nj], bb + OFF_BH + brow +
                          (uint32_t)((wn + nj * 16 + kh * 8) * 2));
            #pragma unroll
            for (int mi = 0; mi < 2; mi++) {
                uint32_t ah[4];
                const uint32_t aoff =
                    (uint32_t)((wm + mi * 16 + lrow16) * 80 + (ks + khalf) * 2);
                ldsm_x4(ah, bb + OFF_AH + aoff);
                #pragma unroll
                for (int nj = 0; nj < 4; nj++) {
                    mma16816(acc[mi][nj * 2],     ah, bh[nj]);
                    mma16816(acc[mi][nj * 2 + 1], ah, bh[nj] + 2);
                }
            }
        }
    }

    const int r_in = lane >> 2;
    const int c_in = (lane & 3) * 2;
    float* Cb = C + (size_t)bz * M * N;
    #pragma unroll
    for (int mi = 0; mi < 2; mi++) {
        const int r0 = m0 + wm + mi * 16 + r_in;
        const float b0 = bias[r0];
        const float b1 = bias[r0 + 8];
        #pragma unroll
        for (int ni = 0; ni < 8; ni++) {
            const int col = n0 + wn + ni * 8 + c_in;
            float m0f = cmask[(size_t)bz * N + col];
            float m1f = cmask[(size_t)bz * N + col + 1];
            *(float2*)(Cb + (size_t)r0 * N + col) =
                make_float2((acc[mi][ni][0] + b0) * m0f, (acc[mi][ni][1] + b0) * m1f);
            *(float2*)(Cb + (size_t)(r0 + 8) * N + col) =
                make_float2((acc[mi][ni][2] + b1) * m0f, (acc[mi][ni][3] + b1) * m1f);
        }
    }
}

// ============================================================================
// Tensor-core windowed attention, register-resident P.
// R14: AV is P(fp16) @ Vh only — Vl tile dropped from smem & global.
// QK^T keeps all 3 hi/lo passes.
// ============================================================================
#define AT_QH  0
#define AT_QL  17408
#define AT_KH  34816
#define AT_KL  52224
#define AT_VH  69632
#define AT_MSK 87040    // float[128]
#define AT_SMEM 87552

__global__ __launch_bounds__(256, 2) void attn_mma(const float* __restrict__ masks)
{
    extern __shared__ char sm[];
    const uint32_t smb = smem_u32(sm);
    const int tid = threadIdx.x, warp = tid >> 5, lane = tid & 31;
    const int wh = blockIdx.x, w = wh >> 3, h = wh & 7, b = blockIdx.y;
    const size_t base = ((size_t)b * DKK + h * 64) * SS + (size_t)w * WW;

    {
        const __half* srcs[5] = { g_Qh + base, g_Ql + base, g_Kh + base,
                                  g_Kl + base, g_Vh + base };
        #pragma unroll
        for (int t = 0; t < 5; t++) {
            const uint32_t dstb = smb + t * 17408;
            #pragma unroll
            for (int it = 0; it < 4; it++) {
                int idx = tid + it * 256;
                int row = idx >> 4, ch = idx & 15;
                cp_async16(dstb + row * 272 + ch * 16,
                           srcs[t] + (size_t)row * SS + ch * 8);
            }
        }
        cp_commit();
    }
    if (tid < 32) {
        float4 mv = *(const float4*)(masks + (size_t)b * SS + w * WW + tid * 4);
        *(float4*)(sm + AT_MSK + tid * 16) = mv;
    }
    cp_wait<0>();
    __syncthreads();

    const int r_in = lane >> 2, c_in = (lane & 3) * 2;
    const uint32_t l7 = lane & 7, mh = (lane >> 3) & 1, kh = (lane >> 4) & 1;
    const int i0w = warp * 16;

    // ---- QK^T (3-pass hi/lo) ----
    float acc[16][4];
    #pragma unroll
    for (int f = 0; f < 16; f++)
        #pragma unroll
        for (int t = 0; t < 4; t++) acc[f][t] = 0.f;

    #pragma unroll
    for (int s = 0; s < 4; s++) {
        uint32_t ah[4], al[4];
        const uint32_t aaddr = smb + (s * 16 + kh * 8 + l7) * 272 + (i0w + mh * 8) * 2;
        ldsm_x4_t(ah, aaddr + AT_QH);
        ldsm_x4_t(al, aaddr + AT_QL);
        #pragma unroll
        for (int q = 0; q < 8; q++) {
            const uint32_t baddr = smb + AT_KH +
                (s * 16 + mh * 8 + l7) * 272 + (q * 16 + kh * 8) * 2;
            uint32_t bh4[4], bl4[4];
            ldsm_x4_t(bh4, baddr);
            ldsm_x4_t(bl4, baddr + (AT_KL - AT_KH));
            const int f0 = q * 2;
            mma16816(acc[f0],     ah, bh4);
            mma16816(acc[f0],     al, bh4);
            mma16816(acc[f0],     ah, bl4);
            mma16816(acc[f0 + 1], ah, bh4 + 2);
            mma16816(acc[f0 + 1], al, bh4 + 2);
            mma16816(acc[f0 + 1], ah, bl4 + 2);
        }
    }

    // ---- mask + scale + warp-local softmax ----
    const float* mk = (const float*)(sm + AT_MSK);
    float mx0 = -1e30f, mx1 = -1e30f;
    #pragma unroll
    for (int f = 0; f < 16; f++) {
        const int j = f * 8 + c_in;
        const float mj0 = mk[j], mj1 = mk[j + 1];
        acc[f][0] = (mj0 > 0.f) ? acc[f][0] * 0.125f : -1e9f;
        acc[f][1] = (mj1 > 0.f) ? acc[f][1] * 0.125f : -1e9f;
        acc[f][2] = (mj0 > 0.f) ? acc[f][2] * 0.125f : -1e9f;
        acc[f][3] = (mj1 > 0.f) ? acc[f][3] * 0.125f : -1e9f;
        mx0 = fmaxf(mx0, fmaxf(acc[f][0], acc[f][1]));
        mx1 = fmaxf(mx1, fmaxf(acc[f][2], acc[f][3]));
    }
    mx0 = fmaxf(mx0, __shfl_xor_sync(0xffffffffu, mx0, 1));
    mx0 = fmaxf(mx0, __shfl_xor_sync(0xffffffffu, mx0, 2));
    mx1 = fmaxf(mx1, __shfl_xor_sync(0xffffffffu, mx1, 1));
    mx1 = fmaxf(mx1, __shfl_xor_sync(0xffffffffu, mx1, 2));

    float s0 = 0.f, s1 = 0.f;
    #pragma unroll
    for (int f = 0; f < 16; f++) {
        acc[f][0] = __expf(acc[f][0] - mx0);
        acc[f][1] = __expf(acc[f][1] - mx0);
        acc[f][2] = __expf(acc[f][2] - mx1);
        acc[f][3] = __expf(acc[f][3] - mx1);
        s0 += acc[f][0] + acc[f][1];
        s1 += acc[f][2] + acc[f][3];
    }
    s0 += __shfl_xor_sync(0xffffffffu, s0, 1);
    s0 += __shfl_xor_sync(0xffffffffu, s0, 2);
    s1 += __shfl_xor_sync(0xffffffffu, s1, 1);
    s1 += __shfl_xor_sync(0xffffffffu, s1, 2);

    // ---- pack P (fp16-rn) into A-operand registers ----
    uint32_t pAh[8][4];
    #pragma unroll
    for (int s = 0; s < 8; s++) {
        #pragma unroll
        for (int hf = 0; hf < 2; hf++) {
            const int f = 2 * s + hf;
            #pragma unroll
            for (int pr = 0; pr < 2; pr++) {
                __half2 hp = __halves2half2(__float2half_rn(acc[f][2 * pr]),
                                            __float2half_rn(acc[f][2 * pr + 1]));
                pAh[s][hf * 2 + pr] = *(uint32_t*)&hp;
            }
        }
    }

    // ---- O^T[i][d] = P @ Vh^T ----
    float oc[8][4];
    #pragma unroll
    for (int t = 0; t < 8; t++)
        #pragma unroll
        for (int q = 0; q < 4; q++) oc[t][q] = 0.f;

    #pragma unroll
    for (int s = 0; s < 8; s++) {            // k = j, 16 per step
        #pragma unroll
        for (int dg = 0; dg < 4; dg++) {     // n = d, 16 per group
            uint32_t vh[4];
            const uint32_t vaddr = smb + AT_VH +
                (uint32_t)((dg * 16 + l7 + kh * 8) * 272 + (s * 16 + mh * 8) * 2);
            ldsm_x4(vh, vaddr);
            mma16816(oc[dg * 2],     pAh[s], vh);
            mma16816(oc[dg * 2 + 1], pAh[s], vh + 2);
        }
    }

    // ---- epilogue: /sum (register-local), exact GELU, fp16 store ----
    const float inv0 = 1.f / s0, inv1 = 1.f / s1;
    const int i0 = i0w + r_in;
    #pragma unroll
    for (int t = 0; t < 8; t++) {
        const int d = t * 8 + c_in;
        g_Bo[base + (size_t)d * SS + i0] =
            __float2half_rn(gelu_exact(oc[t][0] * inv0));
        g_Bo[base + (size_t)(d + 1) * SS + i0] =
            __float2half_rn(gelu_exact(oc[t][1] * inv0));
        g_Bo[base + (size_t)d * SS + i0 + 8] =
            __float2half_rn(gelu_exact(oc[t][2] * inv1));
        g_Bo[base + (size_t)(d + 1) * SS + i0 + 8] =
            __float2half_rn(gelu_exact(oc[t][3] * inv1));
    }
}

// ---------------------------------------------------------------------------
extern "C" void kernel_launch(void* const* d_in, const int* in_sizes, int n_in,
                              void* d_out, int out_size)
{
    const float* qk    = (const float*)d_in[0];
    const float* v     = (const float*)d_in[1];
    const float* masks = (const float*)d_in[2];
    const float* Wq    = (const float*)d_in[3];
    const float* bq    = (const float*)d_in[4];
    const float* Wk    = (const float*)d_in[5];
    const float* bk    = (const float*)d_in[6];
    const float* Wv    = (const float*)d_in[7];
    const float* bv    = (const float*)d_in[8];
    const float* Wo    = (const float*)d_in[9];
    const float* bo    = (const float*)d_in[10];
    float* out = (float*)d_out;

    __half *Bqk, *Bv, *Wqh, *Wkh, *Wvh, *Woh;
    cudaGetSymbolAddress((void**)&Bqk, g_Bqk);
    cudaGetSymbolAddress((void**)&Bv,  g_Bv);
    cudaGetSymbolAddress((void**)&Wqh, g_Wqh);
    cudaGetSymbolAddress((void**)&Wkh, g_Wkh);
    cudaGetSymbolAddress((void**)&Wvh, g_Wvh);
    cudaGetSymbolAddress((void**)&Woh, g_Woh);

    cudaFuncSetAttribute(gemm_qkv,
                         cudaFuncAttributeMaxDynamicSharedMemorySize, GSMEM_TOTAL);
    cudaFuncSetAttribute(gemm_out,
                         cudaFuncAttributeMaxDynamicSharedMemorySize, GSMEM_TOTAL);
    cudaFuncSetAttribute(attn_mma,
                         cudaFuncAttributeMaxDynamicSharedMemorySize, AT_SMEM);

    dim3 blk(256);

    // ---- conversions (merged: 2 launches) ----
    const int nW = DKK * DD / 4;               // 131072
    cvt_w4<<<4 * nW / 256, blk>>>((const float4*)Wq, (const float4*)Wk,
                                  (const float4*)Wv, (const float4*)Wo,
                                  (uint2*)Wqh, (uint2*)Wkh, (uint2*)Wvh, (uint2*)Woh);
    const int nX = NB * DD * SS / 4;
    cvt_x2<<<2 * nX / 256, blk>>>((const float4*)qk, (const float4*)v,
                                  (uint2*)Bqk, (uint2*)Bv, nX);

    // ---- merged Q/K/V projections (single launch, 12 y-blocks) ----
    gemm_qkv<<<dim3(32, 12, NB), blk, GSMEM_TOTAL>>>(bq, bk, bv);

    // ---- tensor-core attention + GELU (register P, Vh-only AV) ----
    attn_mma<<<dim3(NWIN * NH, NB), blk, AT_SMEM>>>(masks);

    // ---- output projection + final mask ----
    gemm_out<<<dim3(32, 8, NB), blk, GSMEM_TOTAL>>>(bo, masks, out);
}

// round 16
// speedup vs baseline: 1.2823x; 1.0221x over previous
#include <cuda_runtime.h>
#include <cuda_fp16.h>
#include <math.h>
#include <stdint.h>

#define NB   8
#define SS   4096
#define DD   1024
#define DKK  512
#define NH   8
#define WW   128
#define DH   64
#define NWIN 32   // S / W

// fp16 operand buffers (device globals: allowed)
__device__ __half g_Bqk[(size_t)NB * DD * SS];
__device__ __half g_Bv [(size_t)NB * DD * SS];
__device__ __half g_Bo [(size_t)NB * DKK * SS];
__device__ __half g_Qh[(size_t)NB * DKK * SS], g_Ql[(size_t)NB * DKK * SS];
__device__ __half g_Kh[(size_t)NB * DKK * SS], g_Kl[(size_t)NB * DKK * SS];
__device__ __half g_Vh[(size_t)NB * DKK * SS], g_Vl[(size_t)NB * DKK * SS];
__device__ __half g_Wqh[DKK * DD];
__device__ __half g_Wkh[DKK * DD];
__device__ __half g_Wvh[DKK * DD];
__device__ __half g_Woh[DD * DKK];

// ============================================================================
// PTX helpers (sm_80+ only — compute_103-safe)
// ============================================================================
__device__ __forceinline__ uint32_t smem_u32(const void* p) {
    uint32_t a;
    asm("{ .reg .u64 t; cvta.to.shared.u64 t, %1; cvt.u32.u64 %0, t; }"
        : "=r"(a) : "l"(p));
    return a;
}
__device__ __forceinline__ void ldsm_x4(uint32_t* r, uint32_t addr) {
    asm volatile("ldmatrix.sync.aligned.m8n8.x4.shared.b16 {%0,%1,%2,%3}, [%4];"
                 : "=r"(r[0]), "=r"(r[1]), "=r"(r[2]), "=r"(r[3]) : "r"(addr));
}
__device__ __forceinline__ void ldsm_x4_t(uint32_t* r, uint32_t addr) {
    asm volatile("ldmatrix.sync.aligned.m8n8.x4.trans.shared.b16 {%0,%1,%2,%3}, [%4];"
                 : "=r"(r[0]), "=r"(r[1]), "=r"(r[2]), "=r"(r[3]) : "r"(addr));
}
__device__ __forceinline__ void mma16816(float* d, const uint32_t* a, const uint32_t* b) {
    asm volatile(
        "mma.sync.aligned.m16n8k16.row.col.f32.f16.f16.f32 "
        "{%0,%1,%2,%3},{%4,%5,%6,%7},{%8,%9},{%0,%1,%2,%3};"
        : "+f"(d[0]), "+f"(d[1]), "+f"(d[2]), "+f"(d[3])
        : "r"(a[0]), "r"(a[1]), "r"(a[2]), "r"(a[3]), "r"(b[0]), "r"(b[1]));
}
__device__ __forceinline__ void cp_async16(uint32_t dst, const void* src) {
    asm volatile("cp.async.cg.shared.global [%0], [%1], 16;" :: "r"(dst), "l"(src));
}
__device__ __forceinline__ void cp_commit() {
    asm volatile("cp.async.commit_group;" ::: "memory");
}
template<int N> __device__ __forceinline__ void cp_wait() {
    asm volatile("cp.async.wait_group %0;" :: "n"(N) : "memory");
}
__device__ __forceinline__ float gelu_exact(float x) { return x * normcdff(x); }

// ============================================================================
// Single merged conversion kernel: 4 weight matrices + qk + v -> fp16
// ============================================================================
#define NW4 (DKK * DD / 4)            // 131072 float4 per weight matrix
#define NX4 (NB * DD * SS / 4)        // 2097152 float4 per activation tensor
#define CVT_TOTAL (4 * NW4 + 2 * NX4) // 4718592

__global__ void cvt_all(const float4* __restrict__ wq, const float4* __restrict__ wk,
                        const float4* __restrict__ wv, const float4* __restrict__ wo,
                        const float4* __restrict__ xq, const float4* __restrict__ xv,
                        uint2* __restrict__ dwq, uint2* __restrict__ dwk,
                        uint2* __restrict__ dwv, uint2* __restrict__ dwo,
                        uint2* __restrict__ dxq, uint2* __restrict__ dxv)
{
    int i = blockIdx.x * blockDim.x + threadIdx.x;
    const float4* s;
    uint2* d;
    int j;
    if (i < 4 * NW4) {
        int w = i >> 17;  j = i & (NW4 - 1);
        s = (w == 0) ? wq : (w == 1) ? wk : (w == 2) ? wv : wo;
        d = (w == 0) ? dwq : (w == 1) ? dwk : (w == 2) ? dwv : dwo;
    } else {
        int k = i - 4 * NW4;
        int w = (k >= NX4);  j = w ? (k - NX4) : k;
        s = w ? xv : xq;
        d = w ? dxv : dxq;
    }
    float4 v = s[j];
    unsigned h0 = __half_as_ushort(__float2half_rn(v.x));
    unsigned h1 = __half_as_ushort(__float2half_rn(v.y));
    unsigned h2 = __half_as_ushort(__float2half_rn(v.z));
    unsigned h3 = __half_as_ushort(__float2half_rn(v.w));
    d[j] = make_uint2(h0 | (h1 << 16), h2 | (h3 << 16));
}

// ============================================================================
// GEMM smem layout (R11-proven: CTA 128x128, K-chunk 32, 3 stages)
// ============================================================================
#define OFF_AH   0
#define OFF_BH   10240
#define STAGE_SZ 18944
#define NSTAGE   3
#define GSMEM_TOTAL (NSTAGE * STAGE_SZ)

// ============================================================================
// Merged QKV GEMM: grid (32, 12, NB). by>>2 selects Q/K/V segment.
// C = W @ B[bz] + bias, fp16 hi/lo out (V: hi only — Vl is dead).
// ============================================================================
__global__ __launch_bounds__(256, 2) void gemm_qkv(
    const float* __restrict__ bq, const float* __restrict__ bk,
    const float* __restrict__ bv)
{
    extern __shared__ char sm[];
    const int tid  = threadIdx.x;
    const int warp = tid >> 5;
    const int lane = tid & 31;
    const int bx = blockIdx.x, by = blockIdx.y, bz = blockIdx.z;
    const int seg = by >> 2, byy = by & 3;
    const int n0 = bx * 128, m0 = byy * 128;
    const int wm = (warp >> 1) * 32;
    const int wn = (warp & 1) * 64;
    const int M = DKK, N = SS, K = DD;

    const __half* Ah  = (seg == 0) ? g_Wqh : (seg == 1) ? g_Wkh : g_Wvh;
    const __half* Bgl = (seg == 2) ? g_Bv : g_Bqk;
    const float* bias = (seg == 0) ? bq : (seg == 1) ? bk : bv;
    __half* Ch = ((seg == 0) ? g_Qh : (seg == 1) ? g_Kh : g_Vh) + (size_t)bz * M * N;
    __half* Cl = ((seg == 0) ? g_Ql : (seg == 1) ? g_Kl : g_Vl) + (size_t)bz * M * N;
    const bool writeCl = (seg != 2);

    const __half* Bb = Bgl + (size_t)bz * K * N;
    const uint32_t smb = smem_u32(sm);

    const int ar = tid >> 2, aq = tid & 3;
    const int br = tid >> 4, bq2 = tid & 15;

    auto issue = [&](int c, int st) {
        const uint32_t sb = smb + st * STAGE_SZ;
        const __half* Ahp = Ah + (size_t)m0 * K + c * 32;
        const __half* Bp  = Bb + (size_t)(c * 32) * N + n0;
        #pragma unroll
        for (int it = 0; it < 2; it++) {
            int r = ar + it * 64;
            cp_async16(sb + OFF_AH + (uint32_t)(r * 80 + aq * 16),
                       Ahp + (size_t)r * K + aq * 8);
            int rb = br + it * 16;
            cp_async16(sb + OFF_BH + (uint32_t)(rb * 272 + bq2 * 16),
                       Bp + (size_t)rb * N + bq2 * 8);
        }
    };

    float acc[2][8][4];
    #pragma unroll
    for (int i = 0; i < 2; i++)
        #pragma unroll
        for (int j = 0; j < 8; j++)
            #pragma unroll
            for (int t = 0; t < 4; t++) acc[i][j][t] = 0.f;

    const int nch = K >> 5;
    issue(0, 0); cp_commit();
    issue(1, 1); cp_commit();

    const int lrow16 = lane & 15;
    const int khalf  = (lane >> 4) * 8;
    const uint32_t l7 = lane & 7, mh = (lane >> 3) & 1, kh = (lane >> 4) & 1;

    for (int c = 0; c < nch; c++) {
        cp_wait<1>();
        __syncthreads();
        if (c + 2 < nch) issue(c + 2, (c + 2) % NSTAGE);
        cp_commit();

        const uint32_t bb = smb + (c % NSTAGE) * STAGE_SZ;
        #pragma unroll
        for (int s = 0; s < 2; s++) {
            const int ks = s * 16;
            uint32_t bh[4][4];
            const uint32_t brow = (uint32_t)((ks + mh * 8 + l7) * 272);
            #pragma unroll
            for (int nj = 0; nj < 4; nj++)
                ldsm_x4_t(bh[nj], bb + OFF_BH + brow +
                          (uint32_t)((wn + nj * 16 + kh * 8) * 2));
            #pragma unroll
            for (int mi = 0; mi < 2; mi++) {
                uint32_t ah[4];
                const uint32_t aoff =
                    (uint32_t)((wm + mi * 16 + lrow16) * 80 + (ks + khalf) * 2);
                ldsm_x4(ah, bb + OFF_AH + aoff);
                #pragma unroll
                for (int nj = 0; nj < 4; nj++) {
                    mma16816(acc[mi][nj * 2],     ah, bh[nj]);
                    mma16816(acc[mi][nj * 2 + 1], ah, bh[nj] + 2);
                }
            }
        }
    }

    const int r_in = lane >> 2;
    const int c_in = (lane & 3) * 2;
    #pragma unroll
    for (int mi = 0; mi < 2; mi++) {
        const int r0 = m0 + wm + mi * 16 + r_in;
        const float b0 = bias[r0];
        const float b1 = bias[r0 + 8];
        #pragma unroll
        for (int ni = 0; ni < 8; ni++) {
            const int col = n0 + wn + ni * 8 + c_in;
            float v0 = acc[mi][ni][0] + b0, v1 = acc[mi][ni][1] + b0;
            float v2 = acc[mi][ni][2] + b1, v3 = acc[mi][ni][3] + b1;
            __half h0 = __float2half_rn(v0), h1 = __float2half_rn(v1);
            __half h2 = __float2half_rn(v2), h3 = __float2half_rn(v3);
            *(__half2*)(Ch + (size_t)r0 * N + col)       = __halves2half2(h0, h1);
            *(__half2*)(Ch + (size_t)(r0 + 8) * N + col) = __halves2half2(h2, h3);
            if (writeCl) {
                __half l0 = __float2half_rn(__fsub_rn(v0, __half2float(h0)));
                __half l1 = __float2half_rn(__fsub_rn(v1, __half2float(h1)));
                __half l2 = __float2half_rn(__fsub_rn(v2, __half2float(h2)));
                __half l3 = __float2half_rn(__fsub_rn(v3, __half2float(h3)));
                *(__half2*)(Cl + (size_t)r0 * N + col)       = __halves2half2(l0, l1);
                *(__half2*)(Cl + (size_t)(r0 + 8) * N + col) = __halves2half2(l2, l3);
            }
        }
    }
}

// ============================================================================
// Final projection GEMM: fp32 out with column mask.  (3-stage, R11-proven)
// ============================================================================
__global__ __launch_bounds__(256, 2) void gemm_out(
    const float* __restrict__ bias, const float* __restrict__ cmask,
    float* __restrict__ C)
{
    extern __shared__ char sm[];
    const int tid  = threadIdx.x;
    const int warp = tid >> 5;
    const int lane = tid & 31;
    const int bx = blockIdx.x, by = blockIdx.y, bz = blockIdx.z;
    const int n0 = bx * 128, m0 = by * 128;
    const int wm = (warp >> 1) * 32;
    const int wn = (warp & 1) * 64;
    const int M = DD, N = SS, K = DKK;

    const __half* Bb = g_Bo + (size_t)bz * K * N;
    const uint32_t smb = smem_u32(sm);

    const int ar = tid >> 2, aq = tid & 3;
    const int br = tid >> 4, bq2 = tid & 15;

    auto issue = [&](int c, int st) {
        const uint32_t sb = smb + st * STAGE_SZ;
        const __half* Ahp = g_Woh + (size_t)m0 * K + c * 32;
        const __half* Bp  = Bb + (size_t)(c * 32) * N + n0;
        #pragma unroll
        for (int it = 0; it < 2; it++) {
            int r = ar + it * 64;
            cp_async16(sb + OFF_AH + (uint32_t)(r * 80 + aq * 16),
                       Ahp + (size_t)r * K + aq * 8);
            int rb = br + it * 16;
            cp_async16(sb + OFF_BH + (uint32_t)(rb * 272 + bq2 * 16),
                       Bp + (size_t)rb * N + bq2 * 8);
        }
    };

    float acc[2][8][4];
    #pragma unroll
    for (int i = 0; i < 2; i++)
        #pragma unroll
        for (int j = 0; j < 8; j++)
            #pragma unroll
            for (int t = 0; t < 4; t++) acc[i][j][t] = 0.f;

    const int nch = K >> 5;
    issue(0, 0); cp_commit();
    issue(1, 1); cp_commit();

    const int lrow16 = lane & 15;
    const int khalf  = (lane >> 4) * 8;
    const uint32_t l7 = lane & 7, mh = (lane >> 3) & 1, kh = (lane >> 4) & 1;

    for (int c = 0; c < nch; c++) {
        cp_wait<1>();
        __syncthreads();
        if (c + 2 < nch) issue(c + 2, (c + 2) % NSTAGE);
        cp_commit();

        const uint32_t bb = smb + (c % NSTAGE) * STAGE_SZ;
        #pragma unroll
        for (int s = 0; s < 2; s++) {
            const int ks = s * 16;
            uint32_t bh[4][4];
            const uint32_t brow = (uint32_t)((ks + mh * 8 + l7) * 272);
            #pragma unroll
            for (int nj = 0; nj < 4; nj++)
                ldsm_x4_t(bh[nj], bb + OFF_BH + brow +
                          (uint32_t)((wn + nj * 16 + kh * 8) * 2));
            #pragma unroll
            for (int mi = 0; mi < 2; mi++) {
                uint32_t ah[4];
                const uint32_t aoff =
                    (uint32_t)((wm + mi * 16 + lrow16) * 80 + (ks + khalf) * 2);
                ldsm_x4(ah, bb + OFF_AH + aoff);
                #pragma unroll
                for (int nj = 0; nj < 4; nj++) {
                    mma16816(acc[mi][nj * 2],     ah, bh[nj]);
                    mma16816(acc[mi][nj * 2 + 1], ah, bh[nj] + 2);
                }
            }
        }
    }

    const int r_in = lane >> 2;
    const int c_in = (lane & 3) * 2;
    float* Cb = C + (size_t)bz * M * N;
    #pragma unroll
    for (int mi = 0; mi < 2; mi++) {
        const int r0 = m0 + wm + mi * 16 + r_in;
        const float b0 = bias[r0];
        const float b1 = bias[r0 + 8];
        #pragma unroll
        for (int ni = 0; ni < 8; ni++) {
            const int col = n0 + wn + ni * 8 + c_in;
            float m0f = cmask[(size_t)bz * N + col];
            float m1f = cmask[(size_t)bz * N + col + 1];
            *(float2*)(Cb + (size_t)r0 * N + col) =
                make_float2((acc[mi][ni][0] + b0) * m0f, (acc[mi][ni][1] + b0) * m1f);
            *(float2*)(Cb + (size_t)(r0 + 8) * N + col) =
                make_float2((acc[mi][ni][2] + b1) * m0f, (acc[mi][ni][3] + b1) * m1f);
        }
    }
}

// ============================================================================
// Tensor-core windowed attention, register-resident P (R14-proven):
// QK^T (3-pass hi/lo) -> warp-local softmax -> P fp16 in registers ->
// O^T = P @ Vh^T -> /sum, exact GELU, fp16 store.
// ============================================================================
#define AT_QH  0
#define AT_QL  17408
#define AT_KH  34816
#define AT_KL  52224
#define AT_VH  69632
#define AT_MSK 87040    // float[128]
#define AT_SMEM 87552

__global__ __launch_bounds__(256, 2) void attn_mma(const float* __restrict__ masks)
{
    extern __shared__ char sm[];
    const uint32_t smb = smem_u32(sm);
    const int tid = threadIdx.x, warp = tid >> 5, lane = tid & 31;
    const int wh = blockIdx.x, w = wh >> 3, h = wh & 7, b = blockIdx.y;
    const size_t base = ((size_t)b * DKK + h * 64) * SS + (size_t)w * WW;

    {
        const __half* srcs[5] = { g_Qh + base, g_Ql + base, g_Kh + base,
                                  g_Kl + base, g_Vh + base };
        #pragma unroll
        for (int t = 0; t < 5; t++) {
            const uint32_t dstb = smb + t * 17408;
            #pragma unroll
            for (int it = 0; it < 4; it++) {
                int idx = tid + it * 256;
                int row = idx >> 4, ch = idx & 15;
                cp_async16(dstb + row * 272 + ch * 16,
                           srcs[t] + (size_t)row * SS + ch * 8);
            }
        }
        cp_commit();
    }
    if (tid < 32) {
        float4 mv = *(const float4*)(masks + (size_t)b * SS + w * WW + tid * 4);
        *(float4*)(sm + AT_MSK + tid * 16) = mv;
    }
    cp_wait<0>();
    __syncthreads();

    const int r_in = lane >> 2, c_in = (lane & 3) * 2;
    const uint32_t l7 = lane & 7, mh = (lane >> 3) & 1, kh = (lane >> 4) & 1;
    const int i0w = warp * 16;

    // ---- QK^T (3-pass hi/lo) ----
    float acc[16][4];
    #pragma unroll
    for (int f = 0; f < 16; f++)
        #pragma unroll
        for (int t = 0; t < 4; t++) acc[f][t] = 0.f;

    #pragma unroll
    for (int s = 0; s < 4; s++) {
        uint32_t ah[4], al[4];
        const uint32_t aaddr = smb + (s * 16 + kh * 8 + l7) * 272 + (i0w + mh * 8) * 2;
        ldsm_x4_t(ah, aaddr + AT_QH);
        ldsm_x4_t(al, aaddr + AT_QL);
        #pragma unroll
        for (int q = 0; q < 8; q++) {
            const uint32_t baddr = smb + AT_KH +
                (s * 16 + mh * 8 + l7) * 272 + (q * 16 + kh * 8) * 2;
            uint32_t bh4[4], bl4[4];
            ldsm_x4_t(bh4, baddr);
            ldsm_x4_t(bl4, baddr + (AT_KL - AT_KH));
            const int f0 = q * 2;
            mma16816(acc[f0],     ah, bh4);
            mma16816(acc[f0],     al, bh4);
            mma16816(acc[f0],     ah, bl4);
            mma16816(acc[f0 + 1], ah, bh4 + 2);
            mma16816(acc[f0 + 1], al, bh4 + 2);
            mma16816(acc[f0 + 1], ah, bl4 + 2);
        }
    }

    // ---- mask + scale + warp-local softmax ----
    const float* mk = (const float*)(sm + AT_MSK);
    float mx0 = -1e30f, mx1 = -1e30f;
    #pragma unroll
    for (int f = 0; f < 16; f++) {
        const int j = f * 8 + c_in;
        const float mj0 = mk[j], mj1 = mk[j + 1];
        acc[f][0] = (mj0 > 0.f) ? acc[f][0] * 0.125f : -1e9f;
        acc[f][1] = (mj1 > 0.f) ? acc[f][1] * 0.125f : -1e9f;
        acc[f][2] = (mj0 > 0.f) ? acc[f][2] * 0.125f : -1e9f;
        acc[f][3] = (mj1 > 0.f) ? acc[f][3] * 0.125f : -1e9f;
        mx0 = fmaxf(mx0, fmaxf(acc[f][0], acc[f][1]));
        mx1 = fmaxf(mx1, fmaxf(acc[f][2], acc[f][3]));
    }
    mx0 = fmaxf(mx0, __shfl_xor_sync(0xffffffffu, mx0, 1));
    mx0 = fmaxf(mx0, __shfl_xor_sync(0xffffffffu, mx0, 2));
    mx1 = fmaxf(mx1, __shfl_xor_sync(0xffffffffu, mx1, 1));
    mx1 = fmaxf(mx1, __shfl_xor_sync(0xffffffffu, mx1, 2));

    float s0 = 0.f, s1 = 0.f;
    #pragma unroll
    for (int f = 0; f < 16; f++) {
        acc[f][0] = __expf(acc[f][0] - mx0);
        acc[f][1] = __expf(acc[f][1] - mx0);
        acc[f][2] = __expf(acc[f][2] - mx1);
        acc[f][3] = __expf(acc[f][3] - mx1);
        s0 += acc[f][0] + acc[f][1];
        s1 += acc[f][2] + acc[f][3];
    }
    s0 += __shfl_xor_sync(0xffffffffu, s0, 1);
    s0 += __shfl_xor_sync(0xffffffffu, s0, 2);
    s1 += __shfl_xor_sync(0xffffffffu, s1, 1);
    s1 += __shfl_xor_sync(0xffffffffu, s1, 2);

    // ---- pack P (fp16-rn) into A-operand registers ----
    uint32_t pAh[8][4];
    #pragma unroll
    for (int s = 0; s < 8; s++) {
        #pragma unroll
        for (int hf = 0; hf < 2; hf++) {
            const int f = 2 * s + hf;
            #pragma unroll
            for (int pr = 0; pr < 2; pr++) {
                __half2 hp = __halves2half2(__float2half_rn(acc[f][2 * pr]),
                                            __float2half_rn(acc[f][2 * pr + 1]));
                pAh[s][hf * 2 + pr] = *(uint32_t*)&hp;
            }
        }
    }

    // ---- O^T[i][d] = P @ Vh^T ----
    float oc[8][4];
    #pragma unroll
    for (int t = 0; t < 8; t++)
        #pragma unroll
        for (int q = 0; q < 4; q++) oc[t][q] = 0.f;

    #pragma unroll
    for (int s = 0; s < 8; s++) {            // k = j, 16 per step
        #pragma unroll
        for (int dg = 0; dg < 4; dg++) {     // n = d, 16 per group
            uint32_t vh[4];
            const uint32_t vaddr = smb + AT_VH +
                (uint32_t)((dg * 16 + l7 + kh * 8) * 272 + (s * 16 + mh * 8) * 2);
            ldsm_x4(vh, vaddr);
            mma16816(oc[dg * 2],     pAh[s], vh);
            mma16816(oc[dg * 2 + 1], pAh[s], vh + 2);
        }
    }

    // ---- epilogue: /sum (register-local), exact GELU, fp16 store ----
    const float inv0 = 1.f / s0, inv1 = 1.f / s1;
    const int i0 = i0w + r_in;
    #pragma unroll
    for (int t = 0; t < 8; t++) {
        const int d = t * 8 + c_in;
        g_Bo[base + (size_t)d * SS + i0] =
            __float2half_rn(gelu_exact(oc[t][0] * inv0));
        g_Bo[base + (size_t)(d + 1) * SS + i0] =
            __float2half_rn(gelu_exact(oc[t][1] * inv0));
        g_Bo[base + (size_t)d * SS + i0 + 8] =
            __float2half_rn(gelu_exact(oc[t][2] * inv1));
        g_Bo[base + (size_t)(d + 1) * SS + i0 + 8] =
            __float2half_rn(gelu_exact(oc[t][3] * inv1));
    }
}

// ---------------------------------------------------------------------------
extern "C" void kernel_launch(void* const* d_in, const int* in_sizes, int n_in,
                              void* d_out, int out_size)
{
    const float* qk    = (const float*)d_in[0];
    const float* v     = (const float*)d_in[1];
    const float* masks = (const float*)d_in[2];
    const float* Wq    = (const float*)d_in[3];
    const float* bq    = (const float*)d_in[4];
    const float* Wk    = (const float*)d_in[5];
    const float* bk    = (const float*)d_in[6];
    const float* Wv    = (const float*)d_in[7];
    const float* bv    = (const float*)d_in[8];
    const float* Wo    = (const float*)d_in[9];
    const float* bo    = (const float*)d_in[10];
    float* out = (float*)d_out;

    __half *Bqk, *Bv, *Wqh, *Wkh, *Wvh, *Woh;
    cudaGetSymbolAddress((void**)&Bqk, g_Bqk);
    cudaGetSymbolAddress((void**)&Bv,  g_Bv);
    cudaGetSymbolAddress((void**)&Wqh, g_Wqh);
    cudaGetSymbolAddress((void**)&Wkh, g_Wkh);
    cudaGetSymbolAddress((void**)&Wvh, g_Wvh);
    cudaGetSymbolAddress((void**)&Woh, g_Woh);

    cudaFuncSetAttribute(gemm_qkv,
                         cudaFuncAttributeMaxDynamicSharedMemorySize, GSMEM_TOTAL);
    cudaFuncSetAttribute(gemm_out,
                         cudaFuncAttributeMaxDynamicSharedMemorySize, GSMEM_TOTAL);
    cudaFuncSetAttribute(attn_mma,
                         cudaFuncAttributeMaxDynamicSharedMemorySize, AT_SMEM);

    dim3 blk(256);

    // ---- single merged conversion launch ----
    cvt_all<<<CVT_TOTAL / 256, blk>>>(
        (const float4*)Wq, (const float4*)Wk, (const float4*)Wv, (const float4*)Wo,
        (const float4*)qk, (const float4*)v,
        (uint2*)Wqh, (uint2*)Wkh, (uint2*)Wvh, (uint2*)Woh,
        (uint2*)Bqk, (uint2*)Bv);

    // ---- merged Q/K/V projections (single launch, 12 y-blocks) ----
    gemm_qkv<<<dim3(32, 12, NB), blk, GSMEM_TOTAL>>>(bq, bk, bv);

    // ---- tensor-core attention + GELU (register P, Vh-only AV) ----
    attn_mma<<<dim3(NWIN * NH, NB), blk, AT_SMEM>>>(masks);

    // ---- output projection + final mask ----
    gemm_out<<<dim3(32, 8, NB), blk, GSMEM_TOTAL>>>(bo, masks, out);
}